// round 1
// baseline (speedup 1.0000x reference)
#include <cuda_runtime.h>
#include <math.h>
#include <stdint.h>

// Problem constants
#define L_SEQ   4096
#define N_FFT   8192
#define DM      1024
#define BATCH   8
#define KD      64

// ---------------------------------------------------------------------------
// Device scratch (allocation-free rule: __device__ globals)
// ---------------------------------------------------------------------------
__device__ float2 d_twid[N_FFT / 2];                      // exp(-2*pi*i*k/8192), 32 KB
__device__ float2 d_Kf[(size_t)DM * N_FFT];               // per-channel spectra, bit-reversed, 64 MB
__device__ float  d_G[(size_t)BATCH * DM * L_SEQ];        // gelu(conv + u*D), 128 MB

__device__ __forceinline__ float2 cmul(float2 a, float2 b) {
    return make_float2(a.x * b.x - a.y * b.y, a.x * b.y + a.y * b.x);
}

__device__ __forceinline__ float gelu_exact(float x) {
    return 0.5f * x * (1.0f + erff(x * 0.70710678118654752440f));
}

// ---------------------------------------------------------------------------
// Twiddle table (double-precision generation for accuracy)
// ---------------------------------------------------------------------------
__global__ void twid_kernel() {
    int k = blockIdx.x * blockDim.x + threadIdx.x;
    if (k < N_FFT / 2) {
        double ang = -2.0 * 3.14159265358979323846 * (double)k / (double)N_FFT;
        d_twid[k] = make_float2((float)cos(ang), (float)sin(ang));
    }
}

// ---------------------------------------------------------------------------
// In-smem 8192-pt complex FFT.
//   fft_dif : natural order in  -> bit-reversed out, forward (e^{-i})
//   fft_dit : bit-reversed in   -> natural order out, inverse (e^{+i}), unscaled
// Pointwise products are done in the bit-reversed domain, so no reorder pass.
// NTHR threads cooperate; each stage does 4096 disjoint butterflies.
// ---------------------------------------------------------------------------
template <int NTHR>
__device__ void fft_dif(float2* z, int tid) {
    #pragma unroll 1
    for (int ls = 12; ls >= 0; --ls) {
        __syncthreads();
        int s = 1 << ls;
        for (int t = tid; t < N_FFT / 2; t += NTHR) {
            int off = t & (s - 1);
            int i = ((t >> ls) << (ls + 1)) + off;
            float2 a = z[i], b = z[i + s];
            z[i] = make_float2(a.x + b.x, a.y + b.y);
            float2 d = make_float2(a.x - b.x, a.y - b.y);
            float2 w = d_twid[off << (12 - ls)];
            z[i + s] = cmul(d, w);
        }
    }
    __syncthreads();
}

template <int NTHR>
__device__ void fft_dit_inv(float2* z, int tid) {
    #pragma unroll 1
    for (int ls = 0; ls <= 12; ++ls) {
        __syncthreads();
        int s = 1 << ls;
        for (int t = tid; t < N_FFT / 2; t += NTHR) {
            int off = t & (s - 1);
            int i = ((t >> ls) << (ls + 1)) + off;
            float2 w = d_twid[off << (12 - ls)];
            w.y = -w.y;  // conjugate for inverse
            float2 b = cmul(z[i + s], w);
            float2 a = z[i];
            z[i]     = make_float2(a.x + b.x, a.y + b.y);
            z[i + s] = make_float2(a.x - b.x, a.y - b.y);
        }
    }
    __syncthreads();
}

// ---------------------------------------------------------------------------
// Multiscale kernel construction (reference _interp_linear + concat).
// Segments: [0,64)=k0 s1, [64,128)=k1 s1, [2^(i+5),2^(i+6))=k_i scale 2^(i-1).
// ---------------------------------------------------------------------------
__device__ __forceinline__ float build_k(const float* const* kp, int c, int l) {
    int seg, j, s;
    if (l < 64)       { seg = 0; j = l;      s = 1; }
    else if (l < 128) { seg = 1; j = l - 64; s = 1; }
    else {
        int hb = 31 - __clz(l);      // 7..11
        seg = hb - 5;                // 2..6
        j   = l - (1 << hb);
        s   = 1 << (seg - 1);
    }
    const float* kk = kp[seg] + c * KD;
    if (s == 1) return kk[j];
    float coord = ((float)j + 0.5f) / (float)s - 0.5f;
    coord = fminf(fmaxf(coord, 0.0f), 63.0f);
    int lo = (int)floorf(coord);
    int hi = min(lo + 1, 63);
    float w = coord - (float)lo;
    return kk[lo] * (1.0f - w) + kk[hi] * w;
}

__device__ __forceinline__ int brev13(int x) { return (int)(__brev((unsigned)x) >> 19); }

// ---------------------------------------------------------------------------
// Build normalized kernel spectra. One block per channel pair (2c, 2c+1):
// pack z = k_{2c} + i*k_{2c+1}, FFT, spectral separation, store bit-reversed.
// ---------------------------------------------------------------------------
#define BKF_THR 512
__global__ __launch_bounds__(BKF_THR) void build_kf_kernel(
    const float* __restrict__ k0, const float* __restrict__ k1,
    const float* __restrict__ k2, const float* __restrict__ k3,
    const float* __restrict__ k4, const float* __restrict__ k5,
    const float* __restrict__ k6)
{
    extern __shared__ float2 z[];
    __shared__ float red0[BKF_THR], red1[BKF_THR];
    int tid = threadIdx.x;
    int c0 = blockIdx.x * 2, c1 = c0 + 1;
    const float* kp[7] = {k0, k1, k2, k3, k4, k5, k6};

    float s0 = 0.f, s1 = 0.f;
    for (int l = tid; l < N_FFT; l += BKF_THR) {
        if (l < L_SEQ) {
            float v0 = build_k(kp, c0, l);
            float v1 = build_k(kp, c1, l);
            z[l] = make_float2(v0, v1);
            s0 += v0 * v0; s1 += v1 * v1;
        } else {
            z[l] = make_float2(0.f, 0.f);
        }
    }
    red0[tid] = s0; red1[tid] = s1;
    __syncthreads();
    for (int o = BKF_THR / 2; o > 0; o >>= 1) {
        if (tid < o) { red0[tid] += red0[tid + o]; red1[tid] += red1[tid + o]; }
        __syncthreads();
    }
    float inv0 = 1.0f / sqrtf(red0[0]);
    float inv1 = 1.0f / sqrtf(red1[0]);
    for (int l = tid; l < L_SEQ; l += BKF_THR) {
        float2 v = z[l];
        z[l] = make_float2(v.x * inv0, v.y * inv1);
    }

    fft_dif<BKF_THR>(z, tid);

    // Separate the two real-signal spectra (bit-reversed-domain pairing).
    float2* Kf0 = d_Kf + (size_t)c0 * N_FFT;
    float2* Kf1 = d_Kf + (size_t)c1 * N_FFT;
    for (int j = tid; j < N_FFT; j += BKF_THR) {
        int m  = brev13(j);
        int pm = (N_FFT - m) & (N_FFT - 1);
        int p  = brev13(pm);
        float2 zj = z[j], zp = z[p];
        Kf0[j] = make_float2(0.5f * (zj.x + zp.x),  0.5f * (zj.y - zp.y));
        Kf1[j] = make_float2(0.5f * (zj.y + zp.y), -0.5f * (zj.x - zp.x));
    }
}

// ---------------------------------------------------------------------------
// Main conv: one block per (channel d, batch-pair bp). Pack two batch rows
// (same kernel!) as one complex signal: conv results are Re/Im of the IFFT.
// Epilogue fuses  + u*D  and exact GELU, writes g to d_G.
// ---------------------------------------------------------------------------
#define CONV_THR 512
__global__ __launch_bounds__(CONV_THR) void conv_kernel(
    const float* __restrict__ u, const float* __restrict__ Dp)
{
    extern __shared__ float2 z[];
    int tid = threadIdx.x;
    int d  = blockIdx.y;
    int bp = blockIdx.x;
    int b0 = bp * 2, b1 = b0 + 1;

    const float* u0 = u + ((size_t)b0 * DM + d) * L_SEQ;
    const float* u1 = u + ((size_t)b1 * DM + d) * L_SEQ;

    float r0[L_SEQ / CONV_THR], r1[L_SEQ / CONV_THR];
    #pragma unroll
    for (int m = 0; m < L_SEQ / CONV_THR; ++m) {
        int l = tid + m * CONV_THR;
        float a = u0[l], b = u1[l];
        r0[m] = a; r1[m] = b;
        z[l] = make_float2(a, b);
    }
    #pragma unroll
    for (int m = L_SEQ / CONV_THR; m < N_FFT / CONV_THR; ++m)
        z[tid + m * CONV_THR] = make_float2(0.f, 0.f);

    fft_dif<CONV_THR>(z, tid);

    const float2* kf = d_Kf + (size_t)d * N_FFT;
    const float scale = 1.0f / (float)N_FFT;   // fold IFFT 1/N into pointwise
    for (int j = tid; j < N_FFT; j += CONV_THR) {
        float2 v = cmul(z[j], kf[j]);
        z[j] = make_float2(v.x * scale, v.y * scale);
    }

    fft_dit_inv<CONV_THR>(z, tid);

    float dd = Dp[d];
    float* g0 = d_G + ((size_t)b0 * DM + d) * L_SEQ;
    float* g1 = d_G + ((size_t)b1 * DM + d) * L_SEQ;
    #pragma unroll
    for (int m = 0; m < L_SEQ / CONV_THR; ++m) {
        int l = tid + m * CONV_THR;
        float2 v = z[l];
        g0[l] = gelu_exact(v.x + r0[m] * dd);
        g1[l] = gelu_exact(v.y + r1[m] * dd);
    }
}

// ---------------------------------------------------------------------------
// Output projection: out[b,v,l] = sum_d W[v,d] * G[b,d,l] + bias[v]
// fp32 SIMT 128x128 tile, BK=8, 256 threads, 8x8 per thread.
// ---------------------------------------------------------------------------
__global__ __launch_bounds__(256) void gemm_kernel(
    const float* __restrict__ W, const float* __restrict__ bias,
    float* __restrict__ out)
{
    __shared__ float As[8][128];   // [k][m]  (W transposed tile)
    __shared__ float Bs[8][128];   // [k][n]

    int b  = blockIdx.z;
    int v0 = blockIdx.y * 128;
    int n0 = blockIdx.x * 128;
    int tid = threadIdx.x;
    int tx = tid & 15, ty = tid >> 4;

    const float* Gb = d_G + (size_t)b * DM * L_SEQ;

    int ar = tid >> 1;            // 0..127: row (v) in tile
    int ac = (tid & 1) * 4;       // 0 or 4: col (k) in tile
    int br = tid >> 5;            // 0..7 : k row
    int bc = (tid & 31) * 4;      // n col

    float acc[8][8];
    #pragma unroll
    for (int i = 0; i < 8; ++i)
        #pragma unroll
        for (int j = 0; j < 8; ++j) acc[i][j] = 0.f;

    for (int k0 = 0; k0 < DM; k0 += 8) {
        float4 av = *(const float4*)&W[(size_t)(v0 + ar) * DM + k0 + ac];
        float4 bv = *(const float4*)&Gb[(size_t)(k0 + br) * L_SEQ + n0 + bc];
        __syncthreads();
        As[ac + 0][ar] = av.x; As[ac + 1][ar] = av.y;
        As[ac + 2][ar] = av.z; As[ac + 3][ar] = av.w;
        *(float4*)&Bs[br][bc] = bv;
        __syncthreads();

        #pragma unroll
        for (int kk = 0; kk < 8; ++kk) {
            float4 a0 = *(float4*)&As[kk][ty * 8];
            float4 a1 = *(float4*)&As[kk][ty * 8 + 4];
            float4 b0 = *(float4*)&Bs[kk][tx * 8];
            float4 b1 = *(float4*)&Bs[kk][tx * 8 + 4];
            float a[8] = {a0.x, a0.y, a0.z, a0.w, a1.x, a1.y, a1.z, a1.w};
            float bb[8] = {b0.x, b0.y, b0.z, b0.w, b1.x, b1.y, b1.z, b1.w};
            #pragma unroll
            for (int i = 0; i < 8; ++i)
                #pragma unroll
                for (int j = 0; j < 8; ++j)
                    acc[i][j] += a[i] * bb[j];
        }
    }

    #pragma unroll
    for (int i = 0; i < 8; ++i) {
        int v = v0 + ty * 8 + i;
        float bvv = bias[v];
        float* op = out + ((size_t)b * DM + v) * L_SEQ + n0 + tx * 8;
        float4 o0 = make_float4(acc[i][0] + bvv, acc[i][1] + bvv,
                                acc[i][2] + bvv, acc[i][3] + bvv);
        float4 o1 = make_float4(acc[i][4] + bvv, acc[i][5] + bvv,
                                acc[i][6] + bvv, acc[i][7] + bvv);
        *(float4*)&op[0] = o0;
        *(float4*)&op[4] = o1;
    }
}

// ---------------------------------------------------------------------------
// Launch
// ---------------------------------------------------------------------------
extern "C" void kernel_launch(void* const* d_in, const int* in_sizes, int n_in,
                              void* d_out, int out_size)
{
    const float* u  = (const float*)d_in[0];
    const float* k0 = (const float*)d_in[1];
    const float* k1 = (const float*)d_in[2];
    const float* k2 = (const float*)d_in[3];
    const float* k3 = (const float*)d_in[4];
    const float* k4 = (const float*)d_in[5];
    const float* k5 = (const float*)d_in[6];
    const float* k6 = (const float*)d_in[7];
    const float* Dv = (const float*)d_in[8];
    const float* Wv = (const float*)d_in[9];
    const float* bv = (const float*)d_in[10];
    float* out = (float*)d_out;

    // 64 KB dynamic smem opt-in (idempotent; safe during graph capture)
    cudaFuncSetAttribute(build_kf_kernel,
                         cudaFuncAttributeMaxDynamicSharedMemorySize, 65536);
    cudaFuncSetAttribute(conv_kernel,
                         cudaFuncAttributeMaxDynamicSharedMemorySize, 65536);

    twid_kernel<<<(N_FFT / 2 + 255) / 256, 256>>>();
    build_kf_kernel<<<DM / 2, BKF_THR, 65536>>>(k0, k1, k2, k3, k4, k5, k6);
    conv_kernel<<<dim3(BATCH / 2, DM), CONV_THR, 65536>>>(u, Dv);
    gemm_kernel<<<dim3(L_SEQ / 128, DM / 128, BATCH), 256>>>(Wv, bv, out);
}

// round 10
// speedup vs baseline: 2.2495x; 2.2495x over previous
#include <cuda_runtime.h>
#include <cuda_bf16.h>
#include <math.h>
#include <stdint.h>

// Problem constants
#define L_SEQ   4096
#define N_FFT   8192
#define DM      1024
#define BATCH   8
#define KD      64

// ---------------------------------------------------------------------------
// Device scratch (allocation-free rule: __device__ globals)
// ---------------------------------------------------------------------------
__device__ float2 d_twid[N_FFT / 2];                        // 32 KB
__device__ float2 d_Kf[(size_t)DM * N_FFT];                 // spectra, DIF order, 64 MB
__device__ __nv_bfloat16 d_Ghi[(size_t)BATCH * DM * L_SEQ]; // 64 MB
__device__ __nv_bfloat16 d_Glo[(size_t)BATCH * DM * L_SEQ]; // 64 MB
__device__ __nv_bfloat16 d_Whi[DM * DM];
__device__ __nv_bfloat16 d_Wlo[DM * DM];

__device__ __forceinline__ float2 cmul(float2 a, float2 b) {
    return make_float2(a.x * b.x - a.y * b.y, a.x * b.y + a.y * b.x);
}
__device__ __forceinline__ float2 cmulc(float2 a, float2 w) {  // a * conj(w)
    return make_float2(a.x * w.x + a.y * w.y, a.y * w.x - a.x * w.y);
}
__device__ __forceinline__ float2 cadd(float2 a, float2 b) {
    return make_float2(a.x + b.x, a.y + b.y);
}
__device__ __forceinline__ float2 csub(float2 a, float2 b) {
    return make_float2(a.x - b.x, a.y - b.y);
}
__device__ __forceinline__ float gelu_exact(float x) {
    return 0.5f * x * (1.0f + erff(x * 0.70710678118654752440f));
}
__device__ __forceinline__ uint32_t smem_u32(const void* p) {
    uint32_t a;
    asm("{ .reg .u64 t; cvta.to.shared.u64 t, %1; cvt.u32.u64 %0, t; }"
        : "=r"(a) : "l"(p));
    return a;
}

// ---------------------------------------------------------------------------
// Twiddles
// ---------------------------------------------------------------------------
__global__ void twid_kernel() {
    int k = blockIdx.x * blockDim.x + threadIdx.x;
    if (k < N_FFT / 2) {
        double ang = -2.0 * 3.14159265358979323846 * (double)k / (double)N_FFT;
        d_twid[k] = make_float2((float)cos(ang), (float)sin(ang));
    }
}

// ---------------------------------------------------------------------------
// Radix-8 register passes over smem: 3 radix-2 stages per round trip, same
// stage order/twiddles as plain radix-2 DIF/DIT (bit-reversed domain intact).
// Forward pass covers DIF stages lt, lt-1, lt-2; inverse covers DIT lt-2..lt.
// ---------------------------------------------------------------------------
template <int NTHR>
__device__ __forceinline__ void pass8_fwd(float2* __restrict__ z, int tid, int lt) {
    int s4 = 1 << (lt - 2);
    __syncthreads();
    #pragma unroll 1
    for (int t = tid; t < N_FFT / 8; t += NTHR) {
        int o = t & (s4 - 1);
        int p = ((t >> (lt - 2)) << (lt + 1)) + o;
        float2 v[8];
        #pragma unroll
        for (int k = 0; k < 8; ++k) v[k] = z[p + k * s4];
        #pragma unroll
        for (int k = 0; k < 4; ++k) {                       // stage lt
            float2 a = v[k], b = v[k + 4];
            float2 w = d_twid[(o + k * s4) << (12 - lt)];
            v[k] = cadd(a, b);
            v[k + 4] = cmul(csub(a, b), w);
        }
        #pragma unroll
        for (int h = 0; h < 2; ++h)                         // stage lt-1
            #pragma unroll
            for (int k = 0; k < 2; ++k) {
                int i0 = h * 4 + k;
                float2 a = v[i0], b = v[i0 + 2];
                float2 w = d_twid[(o + k * s4) << (13 - lt)];
                v[i0] = cadd(a, b);
                v[i0 + 2] = cmul(csub(a, b), w);
            }
        {                                                   // stage lt-2
            float2 w = d_twid[o << (14 - lt)];
            #pragma unroll
            for (int q = 0; q < 4; ++q) {
                float2 a = v[2 * q], b = v[2 * q + 1];
                v[2 * q] = cadd(a, b);
                v[2 * q + 1] = cmul(csub(a, b), w);
            }
        }
        #pragma unroll
        for (int k = 0; k < 8; ++k) z[p + k * s4] = v[k];
    }
}

template <int NTHR>
__device__ __forceinline__ void pass8_inv(float2* __restrict__ z, int tid, int lt) {
    int s4 = 1 << (lt - 2);
    __syncthreads();
    #pragma unroll 1
    for (int t = tid; t < N_FFT / 8; t += NTHR) {
        int o = t & (s4 - 1);
        int p = ((t >> (lt - 2)) << (lt + 1)) + o;
        float2 v[8];
        #pragma unroll
        for (int k = 0; k < 8; ++k) v[k] = z[p + k * s4];
        {                                                   // stage lt-2
            float2 w = d_twid[o << (14 - lt)];
            #pragma unroll
            for (int q = 0; q < 4; ++q) {
                float2 a = v[2 * q];
                float2 b = cmulc(v[2 * q + 1], w);
                v[2 * q] = cadd(a, b);
                v[2 * q + 1] = csub(a, b);
            }
        }
        #pragma unroll
        for (int h = 0; h < 2; ++h)                         // stage lt-1
            #pragma unroll
            for (int k = 0; k < 2; ++k) {
                int i0 = h * 4 + k;
                float2 w = d_twid[(o + k * s4) << (13 - lt)];
                float2 a = v[i0];
                float2 b = cmulc(v[i0 + 2], w);
                v[i0] = cadd(a, b);
                v[i0 + 2] = csub(a, b);
            }
        #pragma unroll
        for (int k = 0; k < 4; ++k) {                       // stage lt
            float2 w = d_twid[(o + k * s4) << (12 - lt)];
            float2 a = v[k];
            float2 b = cmulc(v[k + 4], w);
            v[k] = cadd(a, b);
            v[k + 4] = csub(a, b);
        }
        #pragma unroll
        for (int k = 0; k < 8; ++k) z[p + k * s4] = v[k];
    }
}

// ---------------------------------------------------------------------------
// Multiscale kernel construction
// ---------------------------------------------------------------------------
__device__ __forceinline__ float build_k(const float* const* kp, int c, int l) {
    int seg, j, s;
    if (l < 64)       { seg = 0; j = l;      s = 1; }
    else if (l < 128) { seg = 1; j = l - 64; s = 1; }
    else {
        int hb = 31 - __clz(l);
        seg = hb - 5;
        j   = l - (1 << hb);
        s   = 1 << (seg - 1);
    }
    const float* kk = kp[seg] + c * KD;
    if (s == 1) return kk[j];
    float coord = ((float)j + 0.5f) / (float)s - 0.5f;
    coord = fminf(fmaxf(coord, 0.0f), 63.0f);
    int lo = (int)floorf(coord);
    int hi = min(lo + 1, 63);
    float w = coord - (float)lo;
    return kk[lo] * (1.0f - w) + kk[hi] * w;
}

__device__ __forceinline__ int brev13(int x) { return (int)(__brev((unsigned)x) >> 19); }

#define BKF_THR 512
__global__ __launch_bounds__(BKF_THR) void build_kf_kernel(
    const float* __restrict__ k0, const float* __restrict__ k1,
    const float* __restrict__ k2, const float* __restrict__ k3,
    const float* __restrict__ k4, const float* __restrict__ k5,
    const float* __restrict__ k6)
{
    extern __shared__ float2 z[];
    __shared__ float red0[BKF_THR], red1[BKF_THR];
    int tid = threadIdx.x;
    int c0 = blockIdx.x * 2, c1 = c0 + 1;
    const float* kp[7] = {k0, k1, k2, k3, k4, k5, k6};

    float s0 = 0.f, s1 = 0.f;
    for (int l = tid; l < N_FFT; l += BKF_THR) {
        if (l < L_SEQ) {
            float v0 = build_k(kp, c0, l);
            float v1 = build_k(kp, c1, l);
            z[l] = make_float2(v0, v1);
            s0 += v0 * v0; s1 += v1 * v1;
        } else {
            z[l] = make_float2(0.f, 0.f);
        }
    }
    red0[tid] = s0; red1[tid] = s1;
    __syncthreads();
    for (int o = BKF_THR / 2; o > 0; o >>= 1) {
        if (tid < o) { red0[tid] += red0[tid + o]; red1[tid] += red1[tid + o]; }
        __syncthreads();
    }
    float inv0 = 1.0f / sqrtf(red0[0]);
    float inv1 = 1.0f / sqrtf(red1[0]);
    for (int l = tid; l < L_SEQ; l += BKF_THR) {
        float2 v = z[l];
        z[l] = make_float2(v.x * inv0, v.y * inv1);
    }

    pass8_fwd<BKF_THR>(z, tid, 12);
    pass8_fwd<BKF_THR>(z, tid, 9);
    pass8_fwd<BKF_THR>(z, tid, 6);
    pass8_fwd<BKF_THR>(z, tid, 3);
    __syncthreads();
    for (int t = tid; t < N_FFT / 2; t += BKF_THR) {  // final stage 0, w = 1
        float2 a = z[2 * t], b = z[2 * t + 1];
        z[2 * t] = cadd(a, b);
        z[2 * t + 1] = csub(a, b);
    }
    __syncthreads();

    float2* Kf0 = d_Kf + (size_t)c0 * N_FFT;
    float2* Kf1 = d_Kf + (size_t)c1 * N_FFT;
    for (int j = tid; j < N_FFT; j += BKF_THR) {
        int m  = brev13(j);
        int pm = (N_FFT - m) & (N_FFT - 1);
        int p  = brev13(pm);
        float2 zj = z[j], zp = z[p];
        Kf0[j] = make_float2(0.5f * (zj.x + zp.x),  0.5f * (zj.y - zp.y));
        Kf1[j] = make_float2(0.5f * (zj.y + zp.y), -0.5f * (zj.x - zp.x));
    }
}

// ---------------------------------------------------------------------------
// W split (fp32 -> bf16 hi + lo)
// ---------------------------------------------------------------------------
__global__ void wsplit_kernel(const float* __restrict__ W) {
    int i = blockIdx.x * blockDim.x + threadIdx.x;
    if (i < DM * DM) {
        float w = W[i];
        __nv_bfloat16 hi = __float2bfloat16(w);
        d_Whi[i] = hi;
        d_Wlo[i] = __float2bfloat16(w - __bfloat162float(hi));
    }
}

// ---------------------------------------------------------------------------
// Conv: one block per (channel d, batch-pair). Two batch rows packed complex.
// Epilogue fuses +u*D, exact GELU, and bf16 hi/lo split for the MMA GEMM.
// ---------------------------------------------------------------------------
#define CONV_THR 512
__global__ __launch_bounds__(CONV_THR) void conv_kernel(
    const float* __restrict__ u, const float* __restrict__ Dp)
{
    extern __shared__ float2 z[];
    int tid = threadIdx.x;
    int d  = blockIdx.y;
    int bp = blockIdx.x;
    int b0 = bp * 2, b1 = b0 + 1;

    const float* u0 = u + ((size_t)b0 * DM + d) * L_SEQ;
    const float* u1 = u + ((size_t)b1 * DM + d) * L_SEQ;

    float r0[L_SEQ / CONV_THR], r1[L_SEQ / CONV_THR];
    #pragma unroll
    for (int m = 0; m < L_SEQ / CONV_THR; ++m) {
        int l = tid + m * CONV_THR;
        float a = u0[l], b = u1[l];
        r0[m] = a; r1[m] = b;
        z[l] = make_float2(a, b);
    }
    #pragma unroll
    for (int m = L_SEQ / CONV_THR; m < N_FFT / CONV_THR; ++m)
        z[tid + m * CONV_THR] = make_float2(0.f, 0.f);

    pass8_fwd<CONV_THR>(z, tid, 12);
    pass8_fwd<CONV_THR>(z, tid, 9);
    pass8_fwd<CONV_THR>(z, tid, 6);
    pass8_fwd<CONV_THR>(z, tid, 3);
    __syncthreads();

    // fused: DIF stage 0 -> pointwise (* Kf * 1/N) -> DIT stage 0
    const float2* kf = d_Kf + (size_t)d * N_FFT;
    const float scale = 1.0f / (float)N_FFT;
    for (int t = tid; t < N_FFT / 2; t += CONV_THR) {
        float2 a = z[2 * t], b = z[2 * t + 1];
        float2 A = cadd(a, b), B = csub(a, b);
        A = cmul(A, kf[2 * t]);
        B = cmul(B, kf[2 * t + 1]);
        A = make_float2(A.x * scale, A.y * scale);
        B = make_float2(B.x * scale, B.y * scale);
        z[2 * t] = cadd(A, B);
        z[2 * t + 1] = csub(A, B);
    }

    pass8_inv<CONV_THR>(z, tid, 3);
    pass8_inv<CONV_THR>(z, tid, 6);
    pass8_inv<CONV_THR>(z, tid, 9);
    pass8_inv<CONV_THR>(z, tid, 12);
    __syncthreads();

    float dd = Dp[d];
    __nv_bfloat16* g0h = d_Ghi + ((size_t)b0 * DM + d) * L_SEQ;
    __nv_bfloat16* g0l = d_Glo + ((size_t)b0 * DM + d) * L_SEQ;
    __nv_bfloat16* g1h = d_Ghi + ((size_t)b1 * DM + d) * L_SEQ;
    __nv_bfloat16* g1l = d_Glo + ((size_t)b1 * DM + d) * L_SEQ;
    #pragma unroll
    for (int m = 0; m < L_SEQ / CONV_THR; ++m) {
        int l = tid + m * CONV_THR;
        float2 v = z[l];
        float y0 = gelu_exact(v.x + r0[m] * dd);
        float y1 = gelu_exact(v.y + r1[m] * dd);
        __nv_bfloat16 h0 = __float2bfloat16(y0);
        __nv_bfloat16 h1 = __float2bfloat16(y1);
        g0h[l] = h0; g0l[l] = __float2bfloat16(y0 - __bfloat162float(h0));
        g1h[l] = h1; g1l[l] = __float2bfloat16(y1 - __bfloat162float(h1));
    }
}

// ---------------------------------------------------------------------------
// Split-bf16 tensor-core GEMM via mma.sync (m16n8k16, HMMA — works on sm_103
// base target, no 'a' features). out[v,n] = sum_d W[v,d]*G[d,n] + bias[v]
//   C = Whi*Ghi + Wlo*Ghi + Whi*Glo  (fp32 accumulators)
// Block tile 128(M) x 128(N) x 32(K), 8 warps (2x4), warp tile 64x32.
// cp.async double-buffered stages; padded smem pitches (80B / 272B) verified
// bank-conflict-free for ldmatrix / ldmatrix.trans phases.
// ---------------------------------------------------------------------------
#define A_PITCH 40           // bf16 elems per row (32 + 8 pad) = 80 B
#define B_PITCH 136          // bf16 elems per row (128 + 8 pad) = 272 B
#define A_MAT   (128 * A_PITCH * 2)   // 10240 B
#define B_MAT   (32 * B_PITCH * 2)    //  8704 B
#define STAGE_B (2 * A_MAT + 2 * B_MAT)  // 37888 B
#define OFF_AHI 0
#define OFF_ALO A_MAT
#define OFF_BHI (2 * A_MAT)
#define OFF_BLO (2 * A_MAT + B_MAT)
#define GEMM_SMEM (2 * STAGE_B)

__device__ __forceinline__ void cp16(uint32_t dst, const void* src) {
    asm volatile("cp.async.cg.shared.global [%0], [%1], 16;"
                 :: "r"(dst), "l"(src) : "memory");
}
#define CP_COMMIT() asm volatile("cp.async.commit_group;" ::: "memory")
#define CP_WAIT(n)  asm volatile("cp.async.wait_group %0;" :: "n"(n) : "memory")

__device__ __forceinline__ void ldm_x4(uint32_t* r, uint32_t addr) {
    asm volatile("ldmatrix.sync.aligned.m8n8.x4.shared.b16 {%0,%1,%2,%3}, [%4];"
                 : "=r"(r[0]), "=r"(r[1]), "=r"(r[2]), "=r"(r[3]) : "r"(addr));
}
__device__ __forceinline__ void ldm_x4_t(uint32_t* r, uint32_t addr) {
    asm volatile("ldmatrix.sync.aligned.m8n8.x4.trans.shared.b16 {%0,%1,%2,%3}, [%4];"
                 : "=r"(r[0]), "=r"(r[1]), "=r"(r[2]), "=r"(r[3]) : "r"(addr));
}
__device__ __forceinline__ void mma16816(float* d, const uint32_t* a, const uint32_t* b) {
    asm volatile(
        "mma.sync.aligned.m16n8k16.row.col.f32.bf16.bf16.f32 "
        "{%0,%1,%2,%3}, {%4,%5,%6,%7}, {%8,%9}, {%0,%1,%2,%3};"
        : "+f"(d[0]), "+f"(d[1]), "+f"(d[2]), "+f"(d[3])
        : "r"(a[0]), "r"(a[1]), "r"(a[2]), "r"(a[3]), "r"(b[0]), "r"(b[1]));
}

__global__ __launch_bounds__(256, 1) void gemm_mma_kernel(
    const float* __restrict__ bias, float* __restrict__ out)
{
    extern __shared__ __align__(16) char sm[];
    int tid = threadIdx.x;
    int wid = tid >> 5, lane = tid & 31;
    int v0 = blockIdx.x * 128;
    int bb = blockIdx.y >> 5;
    int l0 = (blockIdx.y & 31) * 128;

    uint32_t sbase = smem_u32(sm);
    const __nv_bfloat16* Wsrc[2] = { d_Whi, d_Wlo };
    const __nv_bfloat16* Gsrc[2] = { d_Ghi, d_Glo };

    float acc[4][4][4];
    #pragma unroll
    for (int i = 0; i < 4; ++i)
        #pragma unroll
        for (int j = 0; j < 4; ++j)
            #pragma unroll
            for (int q = 0; q < 4; ++q) acc[i][j][q] = 0.f;

    // -------- tile loader (k-chunk c into stage s) --------
    auto load_tile = [&](int c, int s) {
        int k0 = c * 32;
        uint32_t stg = sbase + s * STAGE_B;
        #pragma unroll
        for (int it = 0; it < 4; ++it) {                 // A: 1024 vectors
            int idx = tid + it * 256;
            int m = idx >> 9, r = (idx >> 2) & 127, c4 = idx & 3;
            const __nv_bfloat16* src = Wsrc[m] + (size_t)(v0 + r) * DM + k0 + c4 * 8;
            cp16(stg + (m ? OFF_ALO : OFF_AHI) + r * (A_PITCH * 2) + c4 * 16, src);
        }
        #pragma unroll
        for (int it = 0; it < 4; ++it) {                 // B: 1024 vectors
            int idx = tid + it * 256;
            int m = idx >> 9, r = (idx >> 4) & 31, c4 = idx & 15;
            const __nv_bfloat16* src =
                Gsrc[m] + ((size_t)(bb * DM + k0 + r)) * L_SEQ + l0 + c4 * 8;
            cp16(stg + (m ? OFF_BLO : OFF_BHI) + r * (B_PITCH * 2) + c4 * 16, src);
        }
        CP_COMMIT();
    };

    int wm = (wid >> 2) * 64;
    int wn = (wid & 3) * 32;
    int lr = lane & 15, lc = lane >> 4;

    load_tile(0, 0);
    #pragma unroll 1
    for (int c = 0; c < 32; ++c) {
        int s = c & 1;
        if (c + 1 < 32) load_tile(c + 1, s ^ 1);
        if (c + 1 < 32) { CP_WAIT(1); } else { CP_WAIT(0); }
        __syncthreads();

        uint32_t stg = sbase + s * STAGE_B;
        #pragma unroll
        for (int kk = 0; kk < 2; ++kk) {
            uint32_t aH[4][4], aL[4][4], bH[4][2], bL[4][2];
            #pragma unroll
            for (int mi = 0; mi < 4; ++mi) {
                uint32_t off = (uint32_t)((wm + mi * 16 + lr) * (A_PITCH * 2) +
                                          (kk * 16 + lc * 8) * 2);
                ldm_x4(aH[mi], stg + OFF_AHI + off);
                ldm_x4(aL[mi], stg + OFF_ALO + off);
            }
            #pragma unroll
            for (int n2 = 0; n2 < 2; ++n2) {
                uint32_t off = (uint32_t)((kk * 16 + lr) * (B_PITCH * 2) +
                                          (wn + n2 * 16 + lc * 8) * 2);
                uint32_t t4[4];
                ldm_x4_t(t4, stg + OFF_BHI + off);
                bH[n2 * 2][0] = t4[0]; bH[n2 * 2][1] = t4[1];
                bH[n2 * 2 + 1][0] = t4[2]; bH[n2 * 2 + 1][1] = t4[3];
                ldm_x4_t(t4, stg + OFF_BLO + off);
                bL[n2 * 2][0] = t4[0]; bL[n2 * 2][1] = t4[1];
                bL[n2 * 2 + 1][0] = t4[2]; bL[n2 * 2 + 1][1] = t4[3];
            }
            #pragma unroll
            for (int mi = 0; mi < 4; ++mi)
                #pragma unroll
                for (int nj = 0; nj < 4; ++nj) {
                    mma16816(acc[mi][nj], aH[mi], bH[nj]);
                    mma16816(acc[mi][nj], aL[mi], bH[nj]);
                    mma16816(acc[mi][nj], aH[mi], bL[nj]);
                }
        }
        __syncthreads();
    }

    // -------- epilogue --------
    int g = lane >> 2, tg = lane & 3;
    #pragma unroll
    for (int mi = 0; mi < 4; ++mi) {
        int v = v0 + wm + mi * 16 + g;
        float bv0 = bias[v], bv1 = bias[v + 8];
        #pragma unroll
        for (int nj = 0; nj < 4; ++nj) {
            float* op = out + ((size_t)bb * DM + v) * L_SEQ + l0 + wn + nj * 8 + tg * 2;
            float2 o0 = make_float2(acc[mi][nj][0] + bv0, acc[mi][nj][1] + bv0);
            float2 o1 = make_float2(acc[mi][nj][2] + bv1, acc[mi][nj][3] + bv1);
            *(float2*)op = o0;
            *(float2*)(op + 8 * L_SEQ) = o1;
        }
    }
}

// ---------------------------------------------------------------------------
// Launch
// ---------------------------------------------------------------------------
extern "C" void kernel_launch(void* const* d_in, const int* in_sizes, int n_in,
                              void* d_out, int out_size)
{
    const float* u  = (const float*)d_in[0];
    const float* k0 = (const float*)d_in[1];
    const float* k1 = (const float*)d_in[2];
    const float* k2 = (const float*)d_in[3];
    const float* k3 = (const float*)d_in[4];
    const float* k4 = (const float*)d_in[5];
    const float* k5 = (const float*)d_in[6];
    const float* k6 = (const float*)d_in[7];
    const float* Dv = (const float*)d_in[8];
    const float* Wv = (const float*)d_in[9];
    const float* bv = (const float*)d_in[10];
    float* out = (float*)d_out;

    cudaFuncSetAttribute(build_kf_kernel,
                         cudaFuncAttributeMaxDynamicSharedMemorySize, 65536);
    cudaFuncSetAttribute(conv_kernel,
                         cudaFuncAttributeMaxDynamicSharedMemorySize, 65536);
    cudaFuncSetAttribute(gemm_mma_kernel,
                         cudaFuncAttributeMaxDynamicSharedMemorySize, GEMM_SMEM);

    twid_kernel<<<(N_FFT / 2 + 255) / 256, 256>>>();
    wsplit_kernel<<<(DM * DM) / 256, 256>>>(Wv);
    build_kf_kernel<<<DM / 2, BKF_THR, 65536>>>(k0, k1, k2, k3, k4, k5, k6);
    conv_kernel<<<dim3(BATCH / 2, DM), CONV_THR, 65536>>>(u, Dv);
    gemm_mma_kernel<<<dim3(8, 256), 256, GEMM_SMEM>>>(bv, out);
}

// round 13
// speedup vs baseline: 2.6068x; 1.1589x over previous
#include <cuda_runtime.h>
#include <cuda_bf16.h>
#include <math.h>
#include <stdint.h>

// Problem constants
#define L_SEQ   4096
#define N_FFT   8192
#define DM      1024
#define BATCH   8
#define KD      64

// Padded smem indexing: +1 float2 per 16 elements (kills bank conflicts for
// the 16-block register pass; strided pass8 sweeps stay conflict-free).
#define PIDX(i) ((i) + ((i) >> 4))
#define Z_SMEM_BYTES ((N_FFT + N_FFT / 16) * 8)   // 8704 float2 = 69632 B

// ---------------------------------------------------------------------------
// Device scratch (allocation-free rule: __device__ globals)
// ---------------------------------------------------------------------------
__device__ float2 d_twid[N_FFT / 2];                        // 32 KB
__device__ float2 d_Kf[(size_t)DM * N_FFT];                 // spectra (pre-scaled), DIF order
__device__ __nv_bfloat16 d_Ghi[(size_t)BATCH * DM * L_SEQ]; // 64 MB
__device__ __nv_bfloat16 d_Glo[(size_t)BATCH * DM * L_SEQ]; // 64 MB
__device__ __nv_bfloat16 d_Whi[DM * DM];
__device__ __nv_bfloat16 d_Wlo[DM * DM];

__device__ __forceinline__ float2 cmul(float2 a, float2 b) {
    return make_float2(a.x * b.x - a.y * b.y, a.x * b.y + a.y * b.x);
}
__device__ __forceinline__ float2 cmulc(float2 a, float2 w) {  // a * conj(w)
    return make_float2(a.x * w.x + a.y * w.y, a.y * w.x - a.x * w.y);
}
__device__ __forceinline__ float2 cadd(float2 a, float2 b) {
    return make_float2(a.x + b.x, a.y + b.y);
}
__device__ __forceinline__ float2 csub(float2 a, float2 b) {
    return make_float2(a.x - b.x, a.y - b.y);
}
__device__ __forceinline__ float gelu_exact(float x) {
    return 0.5f * x * (1.0f + erff(x * 0.70710678118654752440f));
}
__device__ __forceinline__ uint32_t smem_u32(const void* p) {
    uint32_t a;
    asm("{ .reg .u64 t; cvta.to.shared.u64 t, %1; cvt.u32.u64 %0, t; }"
        : "=r"(a) : "l"(p));
    return a;
}

// ---------------------------------------------------------------------------
// Twiddles
// ---------------------------------------------------------------------------
__global__ void twid_kernel() {
    int k = blockIdx.x * blockDim.x + threadIdx.x;
    if (k < N_FFT / 2) {
        double ang = -2.0 * 3.14159265358979323846 * (double)k / (double)N_FFT;
        d_twid[k] = make_float2((float)cos(ang), (float)sin(ang));
    }
}

// ---------------------------------------------------------------------------
// Radix-8 register passes over padded smem (3 radix-2 stages per round trip,
// stage order/twiddles identical to plain radix-2 DIF/DIT).
// ---------------------------------------------------------------------------
template <int NTHR>
__device__ __forceinline__ void pass8_fwd(float2* __restrict__ z, int tid, int lt) {
    int s4 = 1 << (lt - 2);
    __syncthreads();
    #pragma unroll 1
    for (int t = tid; t < N_FFT / 8; t += NTHR) {
        int o = t & (s4 - 1);
        int p = ((t >> (lt - 2)) << (lt + 1)) + o;
        float2 v[8];
        #pragma unroll
        for (int k = 0; k < 8; ++k) v[k] = z[PIDX(p + k * s4)];
        #pragma unroll
        for (int k = 0; k < 4; ++k) {                       // stage lt
            float2 a = v[k], b = v[k + 4];
            float2 w = d_twid[(o + k * s4) << (12 - lt)];
            v[k] = cadd(a, b);
            v[k + 4] = cmul(csub(a, b), w);
        }
        #pragma unroll
        for (int h = 0; h < 2; ++h)                         // stage lt-1
            #pragma unroll
            for (int k = 0; k < 2; ++k) {
                int i0 = h * 4 + k;
                float2 a = v[i0], b = v[i0 + 2];
                float2 w = d_twid[(o + k * s4) << (13 - lt)];
                v[i0] = cadd(a, b);
                v[i0 + 2] = cmul(csub(a, b), w);
            }
        {                                                   // stage lt-2
            float2 w = d_twid[o << (14 - lt)];
            #pragma unroll
            for (int q = 0; q < 4; ++q) {
                float2 a = v[2 * q], b = v[2 * q + 1];
                v[2 * q] = cadd(a, b);
                v[2 * q + 1] = cmul(csub(a, b), w);
            }
        }
        #pragma unroll
        for (int k = 0; k < 8; ++k) z[PIDX(p + k * s4)] = v[k];
    }
}

template <int NTHR>
__device__ __forceinline__ void pass8_inv(float2* __restrict__ z, int tid, int lt) {
    int s4 = 1 << (lt - 2);
    __syncthreads();
    #pragma unroll 1
    for (int t = tid; t < N_FFT / 8; t += NTHR) {
        int o = t & (s4 - 1);
        int p = ((t >> (lt - 2)) << (lt + 1)) + o;
        float2 v[8];
        #pragma unroll
        for (int k = 0; k < 8; ++k) v[k] = z[PIDX(p + k * s4)];
        {                                                   // stage lt-2
            float2 w = d_twid[o << (14 - lt)];
            #pragma unroll
            for (int q = 0; q < 4; ++q) {
                float2 a = v[2 * q];
                float2 b = cmulc(v[2 * q + 1], w);
                v[2 * q] = cadd(a, b);
                v[2 * q + 1] = csub(a, b);
            }
        }
        #pragma unroll
        for (int h = 0; h < 2; ++h)                         // stage lt-1
            #pragma unroll
            for (int k = 0; k < 2; ++k) {
                int i0 = h * 4 + k;
                float2 w = d_twid[(o + k * s4) << (13 - lt)];
                float2 a = v[i0];
                float2 b = cmulc(v[i0 + 2], w);
                v[i0] = cadd(a, b);
                v[i0 + 2] = csub(a, b);
            }
        #pragma unroll
        for (int k = 0; k < 4; ++k) {                       // stage lt
            float2 w = d_twid[(o + k * s4) << (12 - lt)];
            float2 a = v[k];
            float2 b = cmulc(v[k + 4], w);
            v[k] = cadd(a, b);
            v[k + 4] = csub(a, b);
        }
        #pragma unroll
        for (int k = 0; k < 8; ++k) z[PIDX(p + k * s4)] = v[k];
    }
}

// ---------------------------------------------------------------------------
// Register-resident 16-point FFT (DIF stages 3..0 / DIT stages 0..3) with
// compile-time root-of-unity twiddles. Operates on one contiguous 16-block.
// ---------------------------------------------------------------------------
#define FC1 0.92387953251128675613f
#define FS1 0.38268343236508977173f
#define FC2 0.70710678118654752440f

__device__ __forceinline__ void fft16_fwd(float2* v) {
    const float2 W16[8] = {{1.f,0.f},{FC1,-FS1},{FC2,-FC2},{FS1,-FC1},
                           {0.f,-1.f},{-FS1,-FC1},{-FC2,-FC2},{-FC1,-FS1}};
    const float2 W8[4]  = {{1.f,0.f},{FC2,-FC2},{0.f,-1.f},{-FC2,-FC2}};
    const float2 W4[2]  = {{1.f,0.f},{0.f,-1.f}};
    #pragma unroll
    for (int j = 0; j < 8; ++j) {                           // stage 3
        float2 a = v[j], b = v[j + 8];
        v[j] = cadd(a, b);
        v[j + 8] = cmul(csub(a, b), W16[j]);
    }
    #pragma unroll
    for (int h = 0; h < 2; ++h)                             // stage 2
        #pragma unroll
        for (int j = 0; j < 4; ++j) {
            int i0 = h * 8 + j;
            float2 a = v[i0], b = v[i0 + 4];
            v[i0] = cadd(a, b);
            v[i0 + 4] = cmul(csub(a, b), W8[j]);
        }
    #pragma unroll
    for (int h = 0; h < 4; ++h)                             // stage 1
        #pragma unroll
        for (int j = 0; j < 2; ++j) {
            int i0 = h * 4 + j;
            float2 a = v[i0], b = v[i0 + 2];
            v[i0] = cadd(a, b);
            v[i0 + 2] = cmul(csub(a, b), W4[j]);
        }
    #pragma unroll
    for (int q = 0; q < 8; ++q) {                           // stage 0
        float2 a = v[2 * q], b = v[2 * q + 1];
        v[2 * q] = cadd(a, b);
        v[2 * q + 1] = csub(a, b);
    }
}

__device__ __forceinline__ void fft16_inv(float2* v) {
    const float2 W16[8] = {{1.f,0.f},{FC1,-FS1},{FC2,-FC2},{FS1,-FC1},
                           {0.f,-1.f},{-FS1,-FC1},{-FC2,-FC2},{-FC1,-FS1}};
    const float2 W8[4]  = {{1.f,0.f},{FC2,-FC2},{0.f,-1.f},{-FC2,-FC2}};
    const float2 W4[2]  = {{1.f,0.f},{0.f,-1.f}};
    #pragma unroll
    for (int q = 0; q < 8; ++q) {                           // stage 0
        float2 a = v[2 * q], b = v[2 * q + 1];
        v[2 * q] = cadd(a, b);
        v[2 * q + 1] = csub(a, b);
    }
    #pragma unroll
    for (int h = 0; h < 4; ++h)                             // stage 1
        #pragma unroll
        for (int j = 0; j < 2; ++j) {
            int i0 = h * 4 + j;
            float2 a = v[i0];
            float2 b = cmulc(v[i0 + 2], W4[j]);
            v[i0] = cadd(a, b);
            v[i0 + 2] = csub(a, b);
        }
    #pragma unroll
    for (int h = 0; h < 2; ++h)                             // stage 2
        #pragma unroll
        for (int j = 0; j < 4; ++j) {
            int i0 = h * 8 + j;
            float2 a = v[i0];
            float2 b = cmulc(v[i0 + 4], W8[j]);
            v[i0] = cadd(a, b);
            v[i0 + 4] = csub(a, b);
        }
    #pragma unroll
    for (int j = 0; j < 8; ++j) {                           // stage 3
        float2 a = v[j];
        float2 b = cmulc(v[j + 8], W16[j]);
        v[j] = cadd(a, b);
        v[j + 8] = csub(a, b);
    }
}

// ---------------------------------------------------------------------------
// Multiscale kernel construction
// ---------------------------------------------------------------------------
__device__ __forceinline__ float build_k(const float* const* kp, int c, int l) {
    int seg, j, s;
    if (l < 64)       { seg = 0; j = l;      s = 1; }
    else if (l < 128) { seg = 1; j = l - 64; s = 1; }
    else {
        int hb = 31 - __clz(l);
        seg = hb - 5;
        j   = l - (1 << hb);
        s   = 1 << (seg - 1);
    }
    const float* kk = kp[seg] + c * KD;
    if (s == 1) return kk[j];
    float coord = ((float)j + 0.5f) / (float)s - 0.5f;
    coord = fminf(fmaxf(coord, 0.0f), 63.0f);
    int lo = (int)floorf(coord);
    int hi = min(lo + 1, 63);
    float w = coord - (float)lo;
    return kk[lo] * (1.0f - w) + kk[hi] * w;
}

__device__ __forceinline__ int brev13(int x) { return (int)(__brev((unsigned)x) >> 19); }

#define BKF_THR 512
__global__ __launch_bounds__(BKF_THR) void build_kf_kernel(
    const float* __restrict__ k0, const float* __restrict__ k1,
    const float* __restrict__ k2, const float* __restrict__ k3,
    const float* __restrict__ k4, const float* __restrict__ k5,
    const float* __restrict__ k6)
{
    extern __shared__ float2 z[];
    __shared__ float red0[BKF_THR], red1[BKF_THR];
    int tid = threadIdx.x;
    int c0 = blockIdx.x * 2, c1 = c0 + 1;
    const float* kp[7] = {k0, k1, k2, k3, k4, k5, k6};

    float s0 = 0.f, s1 = 0.f;
    for (int l = tid; l < N_FFT; l += BKF_THR) {
        if (l < L_SEQ) {
            float v0 = build_k(kp, c0, l);
            float v1 = build_k(kp, c1, l);
            z[PIDX(l)] = make_float2(v0, v1);
            s0 += v0 * v0; s1 += v1 * v1;
        } else {
            z[PIDX(l)] = make_float2(0.f, 0.f);
        }
    }
    red0[tid] = s0; red1[tid] = s1;
    __syncthreads();
    for (int o = BKF_THR / 2; o > 0; o >>= 1) {
        if (tid < o) { red0[tid] += red0[tid + o]; red1[tid] += red1[tid + o]; }
        __syncthreads();
    }
    float inv0 = 1.0f / sqrtf(red0[0]);
    float inv1 = 1.0f / sqrtf(red1[0]);
    for (int l = tid; l < L_SEQ; l += BKF_THR) {
        float2 v = z[PIDX(l)];
        z[PIDX(l)] = make_float2(v.x * inv0, v.y * inv1);
    }

    pass8_fwd<BKF_THR>(z, tid, 12);
    pass8_fwd<BKF_THR>(z, tid, 9);
    pass8_fwd<BKF_THR>(z, tid, 6);
    __syncthreads();
    {                                   // stages 3..0 in registers
        float2 v[16];
        #pragma unroll
        for (int j = 0; j < 16; ++j) v[j] = z[PIDX(16 * tid + j)];
        fft16_fwd(v);
        #pragma unroll
        for (int j = 0; j < 16; ++j) z[PIDX(16 * tid + j)] = v[j];
    }
    __syncthreads();

    // Separate the two real-signal spectra; fold in 1/N scale for the conv.
    const float hs = 0.5f / (float)N_FFT;
    float2* Kf0 = d_Kf + (size_t)c0 * N_FFT;
    float2* Kf1 = d_Kf + (size_t)c1 * N_FFT;
    for (int j = tid; j < N_FFT; j += BKF_THR) {
        int m  = brev13(j);
        int pm = (N_FFT - m) & (N_FFT - 1);
        int p  = brev13(pm);
        float2 zj = z[PIDX(j)], zp = z[PIDX(p)];
        Kf0[j] = make_float2(hs * (zj.x + zp.x),  hs * (zj.y - zp.y));
        Kf1[j] = make_float2(hs * (zj.y + zp.y), -hs * (zj.x - zp.x));
    }
}

// ---------------------------------------------------------------------------
// W split (fp32 -> bf16 hi + lo)
// ---------------------------------------------------------------------------
__global__ void wsplit_kernel(const float* __restrict__ W) {
    int i = blockIdx.x * blockDim.x + threadIdx.x;
    if (i < DM * DM) {
        float w = W[i];
        __nv_bfloat16 hi = __float2bfloat16(w);
        d_Whi[i] = hi;
        d_Wlo[i] = __float2bfloat16(w - __bfloat162float(hi));
    }
}

// ---------------------------------------------------------------------------
// Conv: one block per (channel d, batch-pair). Two batch rows packed complex.
// 7 smem sweeps total: 3 fwd pass8 + 1 merged register pass (fwd stages 3..0,
// pointwise, inv stages 0..3) + 3 inv pass8. Epilogue fuses +u*D, exact GELU,
// and bf16 hi/lo split for the MMA GEMM.
// ---------------------------------------------------------------------------
#define CONV_THR 512
__global__ __launch_bounds__(CONV_THR, 2) void conv_kernel(
    const float* __restrict__ u, const float* __restrict__ Dp)
{
    extern __shared__ float2 z[];
    int tid = threadIdx.x;
    int d  = blockIdx.y;
    int bp = blockIdx.x;
    int b0 = bp * 2, b1 = b0 + 1;

    const float* u0 = u + ((size_t)b0 * DM + d) * L_SEQ;
    const float* u1 = u + ((size_t)b1 * DM + d) * L_SEQ;

    #pragma unroll
    for (int m = 0; m < L_SEQ / CONV_THR; ++m) {
        int l = tid + m * CONV_THR;
        z[PIDX(l)] = make_float2(u0[l], u1[l]);
    }
    #pragma unroll
    for (int m = L_SEQ / CONV_THR; m < N_FFT / CONV_THR; ++m)
        z[PIDX(tid + m * CONV_THR)] = make_float2(0.f, 0.f);

    pass8_fwd<CONV_THR>(z, tid, 12);
    pass8_fwd<CONV_THR>(z, tid, 9);
    pass8_fwd<CONV_THR>(z, tid, 6);
    __syncthreads();

    // merged: fwd stages 3..0 -> pointwise (* pre-scaled Kf) -> inv stages 0..3
    {
        float2 v[16];
        #pragma unroll
        for (int j = 0; j < 16; ++j) v[j] = z[PIDX(16 * tid + j)];
        fft16_fwd(v);
        const float4* kf4 = (const float4*)(d_Kf + (size_t)d * N_FFT + 16 * tid);
        #pragma unroll
        for (int j = 0; j < 8; ++j) {
            float4 kk = kf4[j];
            v[2 * j]     = cmul(v[2 * j],     make_float2(kk.x, kk.y));
            v[2 * j + 1] = cmul(v[2 * j + 1], make_float2(kk.z, kk.w));
        }
        fft16_inv(v);
        #pragma unroll
        for (int j = 0; j < 16; ++j) z[PIDX(16 * tid + j)] = v[j];
    }

    pass8_inv<CONV_THR>(z, tid, 6);
    pass8_inv<CONV_THR>(z, tid, 9);
    pass8_inv<CONV_THR>(z, tid, 12);
    __syncthreads();

    float dd = Dp[d];
    __nv_bfloat16* g0h = d_Ghi + ((size_t)b0 * DM + d) * L_SEQ;
    __nv_bfloat16* g0l = d_Glo + ((size_t)b0 * DM + d) * L_SEQ;
    __nv_bfloat16* g1h = d_Ghi + ((size_t)b1 * DM + d) * L_SEQ;
    __nv_bfloat16* g1l = d_Glo + ((size_t)b1 * DM + d) * L_SEQ;
    #pragma unroll
    for (int m = 0; m < L_SEQ / CONV_THR; ++m) {
        int l = tid + m * CONV_THR;
        float2 v = z[PIDX(l)];
        float y0 = gelu_exact(v.x + u0[l] * dd);
        float y1 = gelu_exact(v.y + u1[l] * dd);
        __nv_bfloat16 h0 = __float2bfloat16(y0);
        __nv_bfloat16 h1 = __float2bfloat16(y1);
        g0h[l] = h0; g0l[l] = __float2bfloat16(y0 - __bfloat162float(h0));
        g1h[l] = h1; g1l[l] = __float2bfloat16(y1 - __bfloat162float(h1));
    }
}

// ---------------------------------------------------------------------------
// Split-bf16 tensor-core GEMM via mma.sync (m16n8k16 HMMA).
//   out[v,n] = sum_d W[v,d]*G[d,n] + bias[v]
//   C = Whi*Ghi + Wlo*Ghi + Whi*Glo  (fp32 accumulators)
// Block tile 128x128x32, 8 warps, cp.async double buffer. (unchanged R10)
// ---------------------------------------------------------------------------
#define A_PITCH 40           // bf16 elems per row (32 + 8 pad) = 80 B
#define B_PITCH 136          // bf16 elems per row (128 + 8 pad) = 272 B
#define A_MAT   (128 * A_PITCH * 2)   // 10240 B
#define B_MAT   (32 * B_PITCH * 2)    //  8704 B
#define STAGE_B (2 * A_MAT + 2 * B_MAT)  // 37888 B
#define OFF_AHI 0
#define OFF_ALO A_MAT
#define OFF_BHI (2 * A_MAT)
#define OFF_BLO (2 * A_MAT + B_MAT)
#define GEMM_SMEM (2 * STAGE_B)

__device__ __forceinline__ void cp16(uint32_t dst, const void* src) {
    asm volatile("cp.async.cg.shared.global [%0], [%1], 16;"
                 :: "r"(dst), "l"(src) : "memory");
}
#define CP_COMMIT() asm volatile("cp.async.commit_group;" ::: "memory")
#define CP_WAIT(n)  asm volatile("cp.async.wait_group %0;" :: "n"(n) : "memory")

__device__ __forceinline__ void ldm_x4(uint32_t* r, uint32_t addr) {
    asm volatile("ldmatrix.sync.aligned.m8n8.x4.shared.b16 {%0,%1,%2,%3}, [%4];"
                 : "=r"(r[0]), "=r"(r[1]), "=r"(r[2]), "=r"(r[3]) : "r"(addr));
}
__device__ __forceinline__ void ldm_x4_t(uint32_t* r, uint32_t addr) {
    asm volatile("ldmatrix.sync.aligned.m8n8.x4.trans.shared.b16 {%0,%1,%2,%3}, [%4];"
                 : "=r"(r[0]), "=r"(r[1]), "=r"(r[2]), "=r"(r[3]) : "r"(addr));
}
__device__ __forceinline__ void mma16816(float* d, const uint32_t* a, const uint32_t* b) {
    asm volatile(
        "mma.sync.aligned.m16n8k16.row.col.f32.bf16.bf16.f32 "
        "{%0,%1,%2,%3}, {%4,%5,%6,%7}, {%8,%9}, {%0,%1,%2,%3};"
        : "+f"(d[0]), "+f"(d[1]), "+f"(d[2]), "+f"(d[3])
        : "r"(a[0]), "r"(a[1]), "r"(a[2]), "r"(a[3]), "r"(b[0]), "r"(b[1]));
}

__global__ __launch_bounds__(256, 1) void gemm_mma_kernel(
    const float* __restrict__ bias, float* __restrict__ out)
{
    extern __shared__ __align__(16) char sm[];
    int tid = threadIdx.x;
    int wid = tid >> 5, lane = tid & 31;
    int v0 = blockIdx.x * 128;
    int bb = blockIdx.y >> 5;
    int l0 = (blockIdx.y & 31) * 128;

    uint32_t sbase = smem_u32(sm);
    const __nv_bfloat16* Wsrc[2] = { d_Whi, d_Wlo };
    const __nv_bfloat16* Gsrc[2] = { d_Ghi, d_Glo };

    float acc[4][4][4];
    #pragma unroll
    for (int i = 0; i < 4; ++i)
        #pragma unroll
        for (int j = 0; j < 4; ++j)
            #pragma unroll
            for (int q = 0; q < 4; ++q) acc[i][j][q] = 0.f;

    auto load_tile = [&](int c, int s) {
        int k0 = c * 32;
        uint32_t stg = sbase + s * STAGE_B;
        #pragma unroll
        for (int it = 0; it < 4; ++it) {                 // A: 1024 vectors
            int idx = tid + it * 256;
            int m = idx >> 9, r = (idx >> 2) & 127, c4 = idx & 3;
            const __nv_bfloat16* src = Wsrc[m] + (size_t)(v0 + r) * DM + k0 + c4 * 8;
            cp16(stg + (m ? OFF_ALO : OFF_AHI) + r * (A_PITCH * 2) + c4 * 16, src);
        }
        #pragma unroll
        for (int it = 0; it < 4; ++it) {                 // B: 1024 vectors
            int idx = tid + it * 256;
            int m = idx >> 9, r = (idx >> 4) & 31, c4 = idx & 15;
            const __nv_bfloat16* src =
                Gsrc[m] + ((size_t)(bb * DM + k0 + r)) * L_SEQ + l0 + c4 * 8;
            cp16(stg + (m ? OFF_BLO : OFF_BHI) + r * (B_PITCH * 2) + c4 * 16, src);
        }
        CP_COMMIT();
    };

    int wm = (wid >> 2) * 64;
    int wn = (wid & 3) * 32;
    int lr = lane & 15, lc = lane >> 4;

    load_tile(0, 0);
    #pragma unroll 1
    for (int c = 0; c < 32; ++c) {
        int s = c & 1;
        if (c + 1 < 32) load_tile(c + 1, s ^ 1);
        if (c + 1 < 32) { CP_WAIT(1); } else { CP_WAIT(0); }
        __syncthreads();

        uint32_t stg = sbase + s * STAGE_B;
        #pragma unroll
        for (int kk = 0; kk < 2; ++kk) {
            uint32_t aH[4][4], aL[4][4], bH[4][2], bL[4][2];
            #pragma unroll
            for (int mi = 0; mi < 4; ++mi) {
                uint32_t off = (uint32_t)((wm + mi * 16 + lr) * (A_PITCH * 2) +
                                          (kk * 16 + lc * 8) * 2);
                ldm_x4(aH[mi], stg + OFF_AHI + off);
                ldm_x4(aL[mi], stg + OFF_ALO + off);
            }
            #pragma unroll
            for (int n2 = 0; n2 < 2; ++n2) {
                uint32_t off = (uint32_t)((kk * 16 + lr) * (B_PITCH * 2) +
                                          (wn + n2 * 16 + lc * 8) * 2);
                uint32_t t4[4];
                ldm_x4_t(t4, stg + OFF_BHI + off);
                bH[n2 * 2][0] = t4[0]; bH[n2 * 2][1] = t4[1];
                bH[n2 * 2 + 1][0] = t4[2]; bH[n2 * 2 + 1][1] = t4[3];
                ldm_x4_t(t4, stg + OFF_BLO + off);
                bL[n2 * 2][0] = t4[0]; bL[n2 * 2][1] = t4[1];
                bL[n2 * 2 + 1][0] = t4[2]; bL[n2 * 2 + 1][1] = t4[3];
            }
            #pragma unroll
            for (int mi = 0; mi < 4; ++mi)
                #pragma unroll
                for (int nj = 0; nj < 4; ++nj) {
                    mma16816(acc[mi][nj], aH[mi], bH[nj]);
                    mma16816(acc[mi][nj], aL[mi], bH[nj]);
                    mma16816(acc[mi][nj], aH[mi], bL[nj]);
                }
        }
        __syncthreads();
    }

    int g = lane >> 2, tg = lane & 3;
    #pragma unroll
    for (int mi = 0; mi < 4; ++mi) {
        int v = v0 + wm + mi * 16 + g;
        float bv0 = bias[v], bv1 = bias[v + 8];
        #pragma unroll
        for (int nj = 0; nj < 4; ++nj) {
            float* op = out + ((size_t)bb * DM + v) * L_SEQ + l0 + wn + nj * 8 + tg * 2;
            float2 o0 = make_float2(acc[mi][nj][0] + bv0, acc[mi][nj][1] + bv0);
            float2 o1 = make_float2(acc[mi][nj][2] + bv1, acc[mi][nj][3] + bv1);
            *(float2*)op = o0;
            *(float2*)(op + 8 * L_SEQ) = o1;
        }
    }
}

// ---------------------------------------------------------------------------
// Launch
// ---------------------------------------------------------------------------
extern "C" void kernel_launch(void* const* d_in, const int* in_sizes, int n_in,
                              void* d_out, int out_size)
{
    const float* u  = (const float*)d_in[0];
    const float* k0 = (const float*)d_in[1];
    const float* k1 = (const float*)d_in[2];
    const float* k2 = (const float*)d_in[3];
    const float* k3 = (const float*)d_in[4];
    const float* k4 = (const float*)d_in[5];
    const float* k5 = (const float*)d_in[6];
    const float* k6 = (const float*)d_in[7];
    const float* Dv = (const float*)d_in[8];
    const float* Wv = (const float*)d_in[9];
    const float* bv = (const float*)d_in[10];
    float* out = (float*)d_out;

    cudaFuncSetAttribute(build_kf_kernel,
                         cudaFuncAttributeMaxDynamicSharedMemorySize, Z_SMEM_BYTES);
    cudaFuncSetAttribute(conv_kernel,
                         cudaFuncAttributeMaxDynamicSharedMemorySize, Z_SMEM_BYTES);
    cudaFuncSetAttribute(gemm_mma_kernel,
                         cudaFuncAttributeMaxDynamicSharedMemorySize, GEMM_SMEM);

    twid_kernel<<<(N_FFT / 2 + 255) / 256, 256>>>();
    wsplit_kernel<<<(DM * DM) / 256, 256>>>(Wv);
    build_kf_kernel<<<DM / 2, BKF_THR, Z_SMEM_BYTES>>>(k0, k1, k2, k3, k4, k5, k6);
    conv_kernel<<<dim3(BATCH / 2, DM), CONV_THR, Z_SMEM_BYTES>>>(u, Dv);
    gemm_mma_kernel<<<dim3(8, 256), 256, GEMM_SMEM>>>(bv, out);
}

// round 14
// speedup vs baseline: 3.3638x; 1.2904x over previous
#include <cuda_runtime.h>
#include <cuda_fp16.h>
#include <math.h>
#include <stdint.h>

// Problem constants
#define L_SEQ   4096
#define N_FFT   8192
#define DM      1024
#define BATCH   8
#define KD      64

// Padded smem indexing: +1 float2 per 16 elements.
#define PIDX(i) ((i) + ((i) >> 4))
#define Z_SMEM_BYTES ((N_FFT + N_FFT / 16) * 8)   // 69632 B

// ---------------------------------------------------------------------------
// Device scratch
// ---------------------------------------------------------------------------
__device__ float2 d_twid[N_FFT / 2];                 // 32 KB
__device__ float2 d_Kf[(size_t)DM * N_FFT];          // spectra (pre-scaled), DIF order
__device__ __half d_Gf[(size_t)BATCH * DM * L_SEQ];  // gelu output, fp16, 64 MB
__device__ __half d_Whf[DM * DM];
__device__ __half d_Wlf[DM * DM];

__device__ __forceinline__ float2 cmul(float2 a, float2 b) {
    return make_float2(a.x * b.x - a.y * b.y, a.x * b.y + a.y * b.x);
}
__device__ __forceinline__ float2 cmulc(float2 a, float2 w) {  // a * conj(w)
    return make_float2(a.x * w.x + a.y * w.y, a.y * w.x - a.x * w.y);
}
__device__ __forceinline__ float2 cadd(float2 a, float2 b) {
    return make_float2(a.x + b.x, a.y + b.y);
}
__device__ __forceinline__ float2 csub(float2 a, float2 b) {
    return make_float2(a.x - b.x, a.y - b.y);
}
__device__ __forceinline__ float gelu_exact(float x) {
    return 0.5f * x * (1.0f + erff(x * 0.70710678118654752440f));
}
__device__ __forceinline__ uint32_t smem_u32(const void* p) {
    uint32_t a;
    asm("{ .reg .u64 t; cvta.to.shared.u64 t, %1; cvt.u32.u64 %0, t; }"
        : "=r"(a) : "l"(p));
    return a;
}

// ---------------------------------------------------------------------------
// Twiddles
// ---------------------------------------------------------------------------
__global__ void twid_kernel() {
    int k = blockIdx.x * blockDim.x + threadIdx.x;
    if (k < N_FFT / 2) {
        double ang = -2.0 * 3.14159265358979323846 * (double)k / (double)N_FFT;
        d_twid[k] = make_float2((float)cos(ang), (float)sin(ang));
    }
}

// ---------------------------------------------------------------------------
// Radix-8 register passes over padded smem (3 radix-2 stages per round trip,
// stage order/twiddles identical to plain radix-2 DIF/DIT).
// ---------------------------------------------------------------------------
template <int NTHR>
__device__ __forceinline__ void pass8_fwd(float2* __restrict__ z, int tid, int lt) {
    int s4 = 1 << (lt - 2);
    __syncthreads();
    #pragma unroll 1
    for (int t = tid; t < N_FFT / 8; t += NTHR) {
        int o = t & (s4 - 1);
        int p = ((t >> (lt - 2)) << (lt + 1)) + o;
        float2 v[8];
        #pragma unroll
        for (int k = 0; k < 8; ++k) v[k] = z[PIDX(p + k * s4)];
        #pragma unroll
        for (int k = 0; k < 4; ++k) {                       // stage lt
            float2 a = v[k], b = v[k + 4];
            float2 w = d_twid[(o + k * s4) << (12 - lt)];
            v[k] = cadd(a, b);
            v[k + 4] = cmul(csub(a, b), w);
        }
        #pragma unroll
        for (int h = 0; h < 2; ++h)                         // stage lt-1
            #pragma unroll
            for (int k = 0; k < 2; ++k) {
                int i0 = h * 4 + k;
                float2 a = v[i0], b = v[i0 + 2];
                float2 w = d_twid[(o + k * s4) << (13 - lt)];
                v[i0] = cadd(a, b);
                v[i0 + 2] = cmul(csub(a, b), w);
            }
        {                                                   // stage lt-2
            float2 w = d_twid[o << (14 - lt)];
            #pragma unroll
            for (int q = 0; q < 4; ++q) {
                float2 a = v[2 * q], b = v[2 * q + 1];
                v[2 * q] = cadd(a, b);
                v[2 * q + 1] = cmul(csub(a, b), w);
            }
        }
        #pragma unroll
        for (int k = 0; k < 8; ++k) z[PIDX(p + k * s4)] = v[k];
    }
}

template <int NTHR>
__device__ __forceinline__ void pass8_inv(float2* __restrict__ z, int tid, int lt) {
    int s4 = 1 << (lt - 2);
    __syncthreads();
    #pragma unroll 1
    for (int t = tid; t < N_FFT / 8; t += NTHR) {
        int o = t & (s4 - 1);
        int p = ((t >> (lt - 2)) << (lt + 1)) + o;
        float2 v[8];
        #pragma unroll
        for (int k = 0; k < 8; ++k) v[k] = z[PIDX(p + k * s4)];
        {                                                   // stage lt-2
            float2 w = d_twid[o << (14 - lt)];
            #pragma unroll
            for (int q = 0; q < 4; ++q) {
                float2 a = v[2 * q];
                float2 b = cmulc(v[2 * q + 1], w);
                v[2 * q] = cadd(a, b);
                v[2 * q + 1] = csub(a, b);
            }
        }
        #pragma unroll
        for (int h = 0; h < 2; ++h)                         // stage lt-1
            #pragma unroll
            for (int k = 0; k < 2; ++k) {
                int i0 = h * 4 + k;
                float2 w = d_twid[(o + k * s4) << (13 - lt)];
                float2 a = v[i0];
                float2 b = cmulc(v[i0 + 2], w);
                v[i0] = cadd(a, b);
                v[i0 + 2] = csub(a, b);
            }
        #pragma unroll
        for (int k = 0; k < 4; ++k) {                       // stage lt
            float2 w = d_twid[(o + k * s4) << (12 - lt)];
            float2 a = v[k];
            float2 b = cmulc(v[k + 4], w);
            v[k] = cadd(a, b);
            v[k + 4] = csub(a, b);
        }
        #pragma unroll
        for (int k = 0; k < 8; ++k) z[PIDX(p + k * s4)] = v[k];
    }
}

// ---------------------------------------------------------------------------
// Register-resident 16-point FFT (DIF stages 3..0 / DIT stages 0..3),
// compile-time root-of-unity twiddles. One contiguous 16-block per thread.
// ---------------------------------------------------------------------------
#define FC1 0.92387953251128675613f
#define FS1 0.38268343236508977173f
#define FC2 0.70710678118654752440f

__device__ __forceinline__ void fft16_fwd(float2* v) {
    const float2 W16[8] = {{1.f,0.f},{FC1,-FS1},{FC2,-FC2},{FS1,-FC1},
                           {0.f,-1.f},{-FS1,-FC1},{-FC2,-FC2},{-FC1,-FS1}};
    const float2 W8[4]  = {{1.f,0.f},{FC2,-FC2},{0.f,-1.f},{-FC2,-FC2}};
    const float2 W4[2]  = {{1.f,0.f},{0.f,-1.f}};
    #pragma unroll
    for (int j = 0; j < 8; ++j) {
        float2 a = v[j], b = v[j + 8];
        v[j] = cadd(a, b);
        v[j + 8] = cmul(csub(a, b), W16[j]);
    }
    #pragma unroll
    for (int h = 0; h < 2; ++h)
        #pragma unroll
        for (int j = 0; j < 4; ++j) {
            int i0 = h * 8 + j;
            float2 a = v[i0], b = v[i0 + 4];
            v[i0] = cadd(a, b);
            v[i0 + 4] = cmul(csub(a, b), W8[j]);
        }
    #pragma unroll
    for (int h = 0; h < 4; ++h)
        #pragma unroll
        for (int j = 0; j < 2; ++j) {
            int i0 = h * 4 + j;
            float2 a = v[i0], b = v[i0 + 2];
            v[i0] = cadd(a, b);
            v[i0 + 2] = cmul(csub(a, b), W4[j]);
        }
    #pragma unroll
    for (int q = 0; q < 8; ++q) {
        float2 a = v[2 * q], b = v[2 * q + 1];
        v[2 * q] = cadd(a, b);
        v[2 * q + 1] = csub(a, b);
    }
}

__device__ __forceinline__ void fft16_inv(float2* v) {
    const float2 W16[8] = {{1.f,0.f},{FC1,-FS1},{FC2,-FC2},{FS1,-FC1},
                           {0.f,-1.f},{-FS1,-FC1},{-FC2,-FC2},{-FC1,-FS1}};
    const float2 W8[4]  = {{1.f,0.f},{FC2,-FC2},{0.f,-1.f},{-FC2,-FC2}};
    const float2 W4[2]  = {{1.f,0.f},{0.f,-1.f}};
    #pragma unroll
    for (int q = 0; q < 8; ++q) {
        float2 a = v[2 * q], b = v[2 * q + 1];
        v[2 * q] = cadd(a, b);
        v[2 * q + 1] = csub(a, b);
    }
    #pragma unroll
    for (int h = 0; h < 4; ++h)
        #pragma unroll
        for (int j = 0; j < 2; ++j) {
            int i0 = h * 4 + j;
            float2 a = v[i0];
            float2 b = cmulc(v[i0 + 2], W4[j]);
            v[i0] = cadd(a, b);
            v[i0 + 2] = csub(a, b);
        }
    #pragma unroll
    for (int h = 0; h < 2; ++h)
        #pragma unroll
        for (int j = 0; j < 4; ++j) {
            int i0 = h * 8 + j;
            float2 a = v[i0];
            float2 b = cmulc(v[i0 + 4], W8[j]);
            v[i0] = cadd(a, b);
            v[i0 + 4] = csub(a, b);
        }
    #pragma unroll
    for (int j = 0; j < 8; ++j) {
        float2 a = v[j];
        float2 b = cmulc(v[j + 8], W16[j]);
        v[j] = cadd(a, b);
        v[j + 8] = csub(a, b);
    }
}

// ---------------------------------------------------------------------------
// Multiscale kernel construction
// ---------------------------------------------------------------------------
__device__ __forceinline__ float build_k(const float* const* kp, int c, int l) {
    int seg, j, s;
    if (l < 64)       { seg = 0; j = l;      s = 1; }
    else if (l < 128) { seg = 1; j = l - 64; s = 1; }
    else {
        int hb = 31 - __clz(l);
        seg = hb - 5;
        j   = l - (1 << hb);
        s   = 1 << (seg - 1);
    }
    const float* kk = kp[seg] + c * KD;
    if (s == 1) return kk[j];
    float coord = ((float)j + 0.5f) / (float)s - 0.5f;
    coord = fminf(fmaxf(coord, 0.0f), 63.0f);
    int lo = (int)floorf(coord);
    int hi = min(lo + 1, 63);
    float w = coord - (float)lo;
    return kk[lo] * (1.0f - w) + kk[hi] * w;
}

__device__ __forceinline__ int brev13(int x) { return (int)(__brev((unsigned)x) >> 19); }

#define BKF_THR 512
__global__ __launch_bounds__(BKF_THR) void build_kf_kernel(
    const float* __restrict__ k0, const float* __restrict__ k1,
    const float* __restrict__ k2, const float* __restrict__ k3,
    const float* __restrict__ k4, const float* __restrict__ k5,
    const float* __restrict__ k6)
{
    extern __shared__ float2 z[];
    __shared__ float red0[BKF_THR], red1[BKF_THR];
    int tid = threadIdx.x;
    int c0 = blockIdx.x * 2, c1 = c0 + 1;
    const float* kp[7] = {k0, k1, k2, k3, k4, k5, k6};

    float s0 = 0.f, s1 = 0.f;
    for (int l = tid; l < N_FFT; l += BKF_THR) {
        if (l < L_SEQ) {
            float v0 = build_k(kp, c0, l);
            float v1 = build_k(kp, c1, l);
            z[PIDX(l)] = make_float2(v0, v1);
            s0 += v0 * v0; s1 += v1 * v1;
        } else {
            z[PIDX(l)] = make_float2(0.f, 0.f);
        }
    }
    red0[tid] = s0; red1[tid] = s1;
    __syncthreads();
    for (int o = BKF_THR / 2; o > 0; o >>= 1) {
        if (tid < o) { red0[tid] += red0[tid + o]; red1[tid] += red1[tid + o]; }
        __syncthreads();
    }
    float inv0 = 1.0f / sqrtf(red0[0]);
    float inv1 = 1.0f / sqrtf(red1[0]);
    for (int l = tid; l < L_SEQ; l += BKF_THR) {
        float2 v = z[PIDX(l)];
        z[PIDX(l)] = make_float2(v.x * inv0, v.y * inv1);
    }

    pass8_fwd<BKF_THR>(z, tid, 12);
    pass8_fwd<BKF_THR>(z, tid, 9);
    pass8_fwd<BKF_THR>(z, tid, 6);
    __syncthreads();
    {
        float2 v[16];
        #pragma unroll
        for (int j = 0; j < 16; ++j) v[j] = z[PIDX(16 * tid + j)];
        fft16_fwd(v);
        #pragma unroll
        for (int j = 0; j < 16; ++j) z[PIDX(16 * tid + j)] = v[j];
    }
    __syncthreads();

    const float hs = 0.5f / (float)N_FFT;
    float2* Kf0 = d_Kf + (size_t)c0 * N_FFT;
    float2* Kf1 = d_Kf + (size_t)c1 * N_FFT;
    for (int j = tid; j < N_FFT; j += BKF_THR) {
        int m  = brev13(j);
        int pm = (N_FFT - m) & (N_FFT - 1);
        int p  = brev13(pm);
        float2 zj = z[PIDX(j)], zp = z[PIDX(p)];
        Kf0[j] = make_float2(hs * (zj.x + zp.x),  hs * (zj.y - zp.y));
        Kf1[j] = make_float2(hs * (zj.y + zp.y), -hs * (zj.x - zp.x));
    }
}

// ---------------------------------------------------------------------------
// W split (fp32 -> fp16 hi + lo; lo lands in subnormal range, still exact
// enough: combined ~19 mantissa bits)
// ---------------------------------------------------------------------------
__global__ void wsplit_kernel(const float* __restrict__ W) {
    int i = blockIdx.x * blockDim.x + threadIdx.x;
    if (i < DM * DM) {
        float w = W[i];
        __half hi = __float2half(w);
        d_Whf[i] = hi;
        d_Wlf[i] = __float2half(w - __half2float(hi));
    }
}

// ---------------------------------------------------------------------------
// Conv: one block per (channel d, batch-pair). Two batch rows packed complex.
// 7 smem sweeps. Epilogue fuses +u*D, exact GELU, fp16 store.
// ---------------------------------------------------------------------------
#define CONV_THR 512
__global__ __launch_bounds__(CONV_THR, 2) void conv_kernel(
    const float* __restrict__ u, const float* __restrict__ Dp)
{
    extern __shared__ float2 z[];
    int tid = threadIdx.x;
    int d  = blockIdx.y;
    int bp = blockIdx.x;
    int b0 = bp * 2, b1 = b0 + 1;

    const float* u0 = u + ((size_t)b0 * DM + d) * L_SEQ;
    const float* u1 = u + ((size_t)b1 * DM + d) * L_SEQ;

    #pragma unroll
    for (int m = 0; m < L_SEQ / CONV_THR; ++m) {
        int l = tid + m * CONV_THR;
        z[PIDX(l)] = make_float2(u0[l], u1[l]);
    }
    #pragma unroll
    for (int m = L_SEQ / CONV_THR; m < N_FFT / CONV_THR; ++m)
        z[PIDX(tid + m * CONV_THR)] = make_float2(0.f, 0.f);

    pass8_fwd<CONV_THR>(z, tid, 12);
    pass8_fwd<CONV_THR>(z, tid, 9);
    pass8_fwd<CONV_THR>(z, tid, 6);
    __syncthreads();

    // merged: fwd stages 3..0 -> pointwise (* pre-scaled Kf) -> inv stages 0..3
    {
        float2 v[16];
        #pragma unroll
        for (int j = 0; j < 16; ++j) v[j] = z[PIDX(16 * tid + j)];
        fft16_fwd(v);
        const float4* kf4 = (const float4*)(d_Kf + (size_t)d * N_FFT + 16 * tid);
        #pragma unroll
        for (int j = 0; j < 8; ++j) {
            float4 kk = kf4[j];
            v[2 * j]     = cmul(v[2 * j],     make_float2(kk.x, kk.y));
            v[2 * j + 1] = cmul(v[2 * j + 1], make_float2(kk.z, kk.w));
        }
        fft16_inv(v);
        #pragma unroll
        for (int j = 0; j < 16; ++j) z[PIDX(16 * tid + j)] = v[j];
    }

    pass8_inv<CONV_THR>(z, tid, 6);
    pass8_inv<CONV_THR>(z, tid, 9);
    pass8_inv<CONV_THR>(z, tid, 12);
    __syncthreads();

    float dd = Dp[d];
    __half* g0 = d_Gf + ((size_t)b0 * DM + d) * L_SEQ;
    __half* g1 = d_Gf + ((size_t)b1 * DM + d) * L_SEQ;
    #pragma unroll
    for (int m = 0; m < L_SEQ / CONV_THR; ++m) {
        int l = tid + m * CONV_THR;
        float2 v = z[PIDX(l)];
        g0[l] = __float2half(gelu_exact(v.x + u0[l] * dd));
        g1[l] = __float2half(gelu_exact(v.y + u1[l] * dd));
    }
}

// ---------------------------------------------------------------------------
// fp16 tensor-core GEMM, 2 passes: out = (Whf + Wlf) * Gf + bias.
// Block tile 128(M) x 256(N) x 32(K); 8 warps (2x4), warp tile 64x64.
// 3-stage cp.async pipeline.
// ---------------------------------------------------------------------------
#define AP 40            // fp16 elems per A row (32 + 8 pad) = 80 B
#define BPCH 264         // fp16 elems per B row (256 + 8 pad) = 528 B
#define A_BYTES (128 * AP * 2)      // 10240
#define B_BYTES (32 * BPCH * 2)     // 16896
#define STG_B (2 * A_BYTES + B_BYTES)   // 37376
#define NSTAGE 3
#define GEMM_SMEM (NSTAGE * STG_B)      // 112128

__device__ __forceinline__ void cp16(uint32_t dst, const void* src) {
    asm volatile("cp.async.cg.shared.global [%0], [%1], 16;"
                 :: "r"(dst), "l"(src) : "memory");
}
#define CP_COMMIT() asm volatile("cp.async.commit_group;" ::: "memory")
#define CP_WAIT(n)  asm volatile("cp.async.wait_group %0;" :: "n"(n) : "memory")

__device__ __forceinline__ void ldm_x4(uint32_t* r, uint32_t addr) {
    asm volatile("ldmatrix.sync.aligned.m8n8.x4.shared.b16 {%0,%1,%2,%3}, [%4];"
                 : "=r"(r[0]), "=r"(r[1]), "=r"(r[2]), "=r"(r[3]) : "r"(addr));
}
__device__ __forceinline__ void ldm_x4_t(uint32_t* r, uint32_t addr) {
    asm volatile("ldmatrix.sync.aligned.m8n8.x4.trans.shared.b16 {%0,%1,%2,%3}, [%4];"
                 : "=r"(r[0]), "=r"(r[1]), "=r"(r[2]), "=r"(r[3]) : "r"(addr));
}
__device__ __forceinline__ void mma16816h(float* d, const uint32_t* a, const uint32_t* b) {
    asm volatile(
        "mma.sync.aligned.m16n8k16.row.col.f32.f16.f16.f32 "
        "{%0,%1,%2,%3}, {%4,%5,%6,%7}, {%8,%9}, {%0,%1,%2,%3};"
        : "+f"(d[0]), "+f"(d[1]), "+f"(d[2]), "+f"(d[3])
        : "r"(a[0]), "r"(a[1]), "r"(a[2]), "r"(a[3]), "r"(b[0]), "r"(b[1]));
}

__global__ __launch_bounds__(256, 1) void gemm_mma_kernel(
    const float* __restrict__ bias, float* __restrict__ out)
{
    extern __shared__ __align__(16) char sm[];
    int tid = threadIdx.x;
    int wid = tid >> 5, lane = tid & 31;
    int v0 = blockIdx.x * 128;
    int bb = blockIdx.y >> 4;
    int l0 = (blockIdx.y & 15) * 256;

    uint32_t sbase = smem_u32(sm);
    const __half* Wsrc[2] = { d_Whf, d_Wlf };

    float acc[4][8][4];
    #pragma unroll
    for (int i = 0; i < 4; ++i)
        #pragma unroll
        for (int j = 0; j < 8; ++j)
            #pragma unroll
            for (int q = 0; q < 4; ++q) acc[i][j][q] = 0.f;

    // tile loader: chunk c -> stage s; always commits (empty group if c>=32)
    auto load_tile = [&](int c, int s) {
        if (c < 32) {
            int k0 = c * 32;
            uint32_t stg = sbase + s * STG_B;
            #pragma unroll
            for (int it = 0; it < 4; ++it) {             // A: Whf/Wlf 128x32
                int idx = tid + it * 256;
                int m = idx >> 9, r = (idx >> 2) & 127, c4 = idx & 3;
                const __half* src = Wsrc[m] + (size_t)(v0 + r) * DM + k0 + c4 * 8;
                cp16(stg + m * A_BYTES + r * (AP * 2) + c4 * 16, src);
            }
            #pragma unroll
            for (int it = 0; it < 4; ++it) {             // B: Gf 32x256
                int idx = tid + it * 256;
                int r = idx >> 5, c4 = idx & 31;
                const __half* src =
                    d_Gf + ((size_t)(bb * DM + k0 + r)) * L_SEQ + l0 + c4 * 8;
                cp16(stg + 2 * A_BYTES + r * (BPCH * 2) + c4 * 16, src);
            }
        }
        CP_COMMIT();
    };

    int wm = (wid >> 2) * 64;
    int wn = (wid & 3) * 64;
    int lr = lane & 15, lc = lane >> 4;

    load_tile(0, 0);
    load_tile(1, 1);
    load_tile(2, 2);

    #pragma unroll 1
    for (int c = 0; c < 32; ++c) {
        int s = c % NSTAGE;
        CP_WAIT(2);
        __syncthreads();

        uint32_t stg = sbase + s * STG_B;
        #pragma unroll
        for (int kk = 0; kk < 2; ++kk) {
            uint32_t aH[4][4], aL[4][4], bF[8][2];
            #pragma unroll
            for (int mi = 0; mi < 4; ++mi) {
                uint32_t off = (uint32_t)((wm + mi * 16 + lr) * (AP * 2) +
                                          (kk * 16 + lc * 8) * 2);
                ldm_x4(aH[mi], stg + off);
                ldm_x4(aL[mi], stg + A_BYTES + off);
            }
            #pragma unroll
            for (int n4 = 0; n4 < 4; ++n4) {
                uint32_t off = (uint32_t)((kk * 16 + lr) * (BPCH * 2) +
                                          (wn + n4 * 16 + lc * 8) * 2);
                uint32_t t4[4];
                ldm_x4_t(t4, stg + 2 * A_BYTES + off);
                bF[n4 * 2][0] = t4[0]; bF[n4 * 2][1] = t4[1];
                bF[n4 * 2 + 1][0] = t4[2]; bF[n4 * 2 + 1][1] = t4[3];
            }
            #pragma unroll
            for (int mi = 0; mi < 4; ++mi)
                #pragma unroll
                for (int nj = 0; nj < 8; ++nj) {
                    mma16816h(acc[mi][nj], aH[mi], bF[nj]);
                    mma16816h(acc[mi][nj], aL[mi], bF[nj]);
                }
        }
        __syncthreads();
        load_tile(c + NSTAGE, s);
    }
    CP_WAIT(0);

    // epilogue
    int g = lane >> 2, tg = lane & 3;
    #pragma unroll
    for (int mi = 0; mi < 4; ++mi) {
        int v = v0 + wm + mi * 16 + g;
        float bv0 = bias[v], bv1 = bias[v + 8];
        #pragma unroll
        for (int nj = 0; nj < 8; ++nj) {
            float* op = out + ((size_t)bb * DM + v) * L_SEQ + l0 + wn + nj * 8 + tg * 2;
            float2 o0 = make_float2(acc[mi][nj][0] + bv0, acc[mi][nj][1] + bv0);
            float2 o1 = make_float2(acc[mi][nj][2] + bv1, acc[mi][nj][3] + bv1);
            *(float2*)op = o0;
            *(float2*)(op + 8 * L_SEQ) = o1;
        }
    }
}

// ---------------------------------------------------------------------------
// Launch
// ---------------------------------------------------------------------------
extern "C" void kernel_launch(void* const* d_in, const int* in_sizes, int n_in,
                              void* d_out, int out_size)
{
    const float* u  = (const float*)d_in[0];
    const float* k0 = (const float*)d_in[1];
    const float* k1 = (const float*)d_in[2];
    const float* k2 = (const float*)d_in[3];
    const float* k3 = (const float*)d_in[4];
    const float* k4 = (const float*)d_in[5];
    const float* k5 = (const float*)d_in[6];
    const float* k6 = (const float*)d_in[7];
    const float* Dv = (const float*)d_in[8];
    const float* Wv = (const float*)d_in[9];
    const float* bv = (const float*)d_in[10];
    float* out = (float*)d_out;

    cudaFuncSetAttribute(build_kf_kernel,
                         cudaFuncAttributeMaxDynamicSharedMemorySize, Z_SMEM_BYTES);
    cudaFuncSetAttribute(conv_kernel,
                         cudaFuncAttributeMaxDynamicSharedMemorySize, Z_SMEM_BYTES);
    cudaFuncSetAttribute(gemm_mma_kernel,
                         cudaFuncAttributeMaxDynamicSharedMemorySize, GEMM_SMEM);

    twid_kernel<<<(N_FFT / 2 + 255) / 256, 256>>>();
    wsplit_kernel<<<(DM * DM) / 256, 256>>>(Wv);
    build_kf_kernel<<<DM / 2, BKF_THR, Z_SMEM_BYTES>>>(k0, k1, k2, k3, k4, k5, k6);
    conv_kernel<<<dim3(BATCH / 2, DM), CONV_THR, Z_SMEM_BYTES>>>(u, Dv);
    gemm_mma_kernel<<<dim3(8, 128), 256, GEMM_SMEM>>>(bv, out);
}

// round 15
// speedup vs baseline: 4.0687x; 1.2096x over previous
#include <cuda_runtime.h>
#include <cuda_fp16.h>
#include <math.h>
#include <stdint.h>

// Problem constants
#define L_SEQ   4096
#define N_FFT   8192
#define DM      1024
#define BATCH   8
#define KD      64

// Padded smem indexing: +1 float2 per 16 elements.
#define PIDX(i) ((i) + ((i) >> 4))
#define Z_SMEM_BYTES ((N_FFT + N_FFT / 16) * 8)   // 69632 B

// ---------------------------------------------------------------------------
// Device scratch
// ---------------------------------------------------------------------------
__device__ float2 d_twid[N_FFT / 2];                 // 32 KB
__device__ float2 d_Kf[(size_t)DM * N_FFT];          // spectra (pre-scaled), DIF order
__device__ __half d_Gf[(size_t)BATCH * DM * L_SEQ];  // gelu output, fp16, 64 MB
__device__ __half d_Whf[DM * DM];
__device__ __half d_Wlf[DM * DM];

__device__ __forceinline__ float2 cmul(float2 a, float2 b) {
    return make_float2(a.x * b.x - a.y * b.y, a.x * b.y + a.y * b.x);
}
__device__ __forceinline__ float2 cmulc(float2 a, float2 w) {  // a * conj(w)
    return make_float2(a.x * w.x + a.y * w.y, a.y * w.x - a.x * w.y);
}
__device__ __forceinline__ float2 cadd(float2 a, float2 b) {
    return make_float2(a.x + b.x, a.y + b.y);
}
__device__ __forceinline__ float2 csub(float2 a, float2 b) {
    return make_float2(a.x - b.x, a.y - b.y);
}
__device__ __forceinline__ float gelu_exact(float x) {
    return 0.5f * x * (1.0f + erff(x * 0.70710678118654752440f));
}
__device__ __forceinline__ uint32_t smem_u32(const void* p) {
    uint32_t a;
    asm("{ .reg .u64 t; cvta.to.shared.u64 t, %1; cvt.u32.u64 %0, t; }"
        : "=r"(a) : "l"(p));
    return a;
}

// Root-of-unity constant tables (forward direction, e^{-i*theta})
#define FC1 0.92387953251128675613f
#define FS1 0.38268343236508977173f
#define FC2 0.70710678118654752440f
#define GC1 0.98078528040323044913f   // cos(pi/16)
#define GS1 0.19509032201612826785f   // sin(pi/16)
#define GC3 0.83146961230254523708f   // cos(3pi/16)
#define GS3 0.55557023301960222474f   // sin(3pi/16)

#define DECL_C16 const float2 C16[8] = {{1.f,0.f},{FC1,-FS1},{FC2,-FC2},{FS1,-FC1}, \
                                        {0.f,-1.f},{-FS1,-FC1},{-FC2,-FC2},{-FC1,-FS1}}
#define DECL_C8  const float2 C8[4]  = {{1.f,0.f},{FC2,-FC2},{0.f,-1.f},{-FC2,-FC2}}
#define DECL_C32 const float2 C32[16] = { \
    {1.f,0.f},{GC1,-GS1},{FC1,-FS1},{GC3,-GS3},{FC2,-FC2},{GS3,-GC3},{FS1,-FC1},{GS1,-GC1}, \
    {0.f,-1.f},{-GS1,-GC1},{-FS1,-FC1},{-GS3,-GC3},{-FC2,-FC2},{-GC3,-GS3},{-FC1,-FS1},{-GC1,-GS1}}

// ---------------------------------------------------------------------------
// Twiddles
// ---------------------------------------------------------------------------
__global__ void twid_kernel() {
    int k = blockIdx.x * blockDim.x + threadIdx.x;
    if (k < N_FFT / 2) {
        double ang = -2.0 * 3.14159265358979323846 * (double)k / (double)N_FFT;
        d_twid[k] = make_float2((float)cos(ang), (float)sin(ang));
    }
}

// ---------------------------------------------------------------------------
// Radix-8 pass (3 radix-2 stages), used only by build_kf_kernel.
// ---------------------------------------------------------------------------
template <int NTHR>
__device__ __forceinline__ void pass8_fwd(float2* __restrict__ z, int tid, int lt) {
    int s4 = 1 << (lt - 2);
    __syncthreads();
    #pragma unroll 1
    for (int t = tid; t < N_FFT / 8; t += NTHR) {
        int o = t & (s4 - 1);
        int p = ((t >> (lt - 2)) << (lt + 1)) + o;
        float2 v[8];
        #pragma unroll
        for (int k = 0; k < 8; ++k) v[k] = z[PIDX(p + k * s4)];
        #pragma unroll
        for (int k = 0; k < 4; ++k) {
            float2 a = v[k], b = v[k + 4];
            float2 w = d_twid[(o + k * s4) << (12 - lt)];
            v[k] = cadd(a, b);
            v[k + 4] = cmul(csub(a, b), w);
        }
        #pragma unroll
        for (int h = 0; h < 2; ++h)
            #pragma unroll
            for (int k = 0; k < 2; ++k) {
                int i0 = h * 4 + k;
                float2 a = v[i0], b = v[i0 + 2];
                float2 w = d_twid[(o + k * s4) << (13 - lt)];
                v[i0] = cadd(a, b);
                v[i0 + 2] = cmul(csub(a, b), w);
            }
        {
            float2 w = d_twid[o << (14 - lt)];
            #pragma unroll
            for (int q = 0; q < 4; ++q) {
                float2 a = v[2 * q], b = v[2 * q + 1];
                v[2 * q] = cadd(a, b);
                v[2 * q + 1] = cmul(csub(a, b), w);
            }
        }
        #pragma unroll
        for (int k = 0; k < 8; ++k) z[PIDX(p + k * s4)] = v[k];
    }
}

// ---------------------------------------------------------------------------
// Radix-16 pass: 4 radix-2 DIF stages (lt..lt-3) per smem round trip.
// One twiddle table load per group; all other twiddles derived:
//   stage lt   : w1 * C16[k]
//   stage lt-1 : w2 * C8[k]      (w2 = w1^2)
//   stage lt-2 : w4 * {1, -i}    (w4 = w2^2)
//   stage lt-3 : w8              (w8 = w4^2)
// Requires NTHR == 512 (= N_FFT/16): exactly one group per thread.
// ---------------------------------------------------------------------------
__device__ __forceinline__ void pass16_fwd(float2* __restrict__ z, int tid, int lt) {
    DECL_C16; DECL_C8;
    int s8 = 1 << (lt - 3);
    __syncthreads();
    int o = tid & (s8 - 1);
    int p = ((tid >> (lt - 3)) << (lt + 1)) + o;
    float2 v[16];
    #pragma unroll
    for (int k = 0; k < 16; ++k) v[k] = z[PIDX(p + k * s8)];
    float2 w1 = d_twid[o << (12 - lt)];
    float2 w2 = cmul(w1, w1);
    float2 w4 = cmul(w2, w2);
    float2 w8 = cmul(w4, w4);
    #pragma unroll
    for (int k = 0; k < 8; ++k) {                       // stage lt
        float2 a = v[k], b = v[k + 8];
        v[k] = cadd(a, b);
        v[k + 8] = cmul(csub(a, b), cmul(w1, C16[k]));
    }
    #pragma unroll
    for (int h = 0; h < 2; ++h)                         // stage lt-1
        #pragma unroll
        for (int k = 0; k < 4; ++k) {
            int i0 = h * 8 + k;
            float2 a = v[i0], b = v[i0 + 4];
            v[i0] = cadd(a, b);
            v[i0 + 4] = cmul(csub(a, b), cmul(w2, C8[k]));
        }
    #pragma unroll
    for (int q = 0; q < 4; ++q)                         // stage lt-2
        #pragma unroll
        for (int k = 0; k < 2; ++k) {
            int i0 = q * 4 + k;
            float2 a = v[i0], b = v[i0 + 2];
            v[i0] = cadd(a, b);
            float2 tw = k ? make_float2(w4.y, -w4.x) : w4;   // w4 * (-i)
            v[i0 + 2] = cmul(csub(a, b), tw);
        }
    #pragma unroll
    for (int r = 0; r < 8; ++r) {                       // stage lt-3
        float2 a = v[2 * r], b = v[2 * r + 1];
        v[2 * r] = cadd(a, b);
        v[2 * r + 1] = cmul(csub(a, b), w8);
    }
    #pragma unroll
    for (int k = 0; k < 16; ++k) z[PIDX(p + k * s8)] = v[k];
}

__device__ __forceinline__ void pass16_inv(float2* __restrict__ z, int tid, int lt) {
    DECL_C16; DECL_C8;
    int s8 = 1 << (lt - 3);
    __syncthreads();
    int o = tid & (s8 - 1);
    int p = ((tid >> (lt - 3)) << (lt + 1)) + o;
    float2 v[16];
    #pragma unroll
    for (int k = 0; k < 16; ++k) v[k] = z[PIDX(p + k * s8)];
    float2 w1 = d_twid[o << (12 - lt)];
    float2 w2 = cmul(w1, w1);
    float2 w4 = cmul(w2, w2);
    float2 w8 = cmul(w4, w4);
    #pragma unroll
    for (int r = 0; r < 8; ++r) {                       // stage lt-3
        float2 a = v[2 * r];
        float2 b = cmulc(v[2 * r + 1], w8);
        v[2 * r] = cadd(a, b);
        v[2 * r + 1] = csub(a, b);
    }
    #pragma unroll
    for (int q = 0; q < 4; ++q)                         // stage lt-2
        #pragma unroll
        for (int k = 0; k < 2; ++k) {
            int i0 = q * 4 + k;
            float2 tw = k ? make_float2(w4.y, -w4.x) : w4;
            float2 a = v[i0];
            float2 b = cmulc(v[i0 + 2], tw);
            v[i0] = cadd(a, b);
            v[i0 + 2] = csub(a, b);
        }
    #pragma unroll
    for (int h = 0; h < 2; ++h)                         // stage lt-1
        #pragma unroll
        for (int k = 0; k < 4; ++k) {
            int i0 = h * 8 + k;
            float2 a = v[i0];
            float2 b = cmulc(v[i0 + 4], cmul(w2, C8[k]));
            v[i0] = cadd(a, b);
            v[i0 + 4] = csub(a, b);
        }
    #pragma unroll
    for (int k = 0; k < 8; ++k) {                       // stage lt
        float2 a = v[k];
        float2 b = cmulc(v[k + 8], cmul(w1, C16[k]));
        v[k] = cadd(a, b);
        v[k + 8] = csub(a, b);
    }
    #pragma unroll
    for (int k = 0; k < 16; ++k) z[PIDX(p + k * s8)] = v[k];
}

// ---------------------------------------------------------------------------
// Register-resident 16-point FFT (DIF stages 3..0 / DIT stages 0..3).
// ---------------------------------------------------------------------------
__device__ __forceinline__ void fft16_fwd(float2* v) {
    DECL_C16; DECL_C8;
    const float2 W4[2]  = {{1.f,0.f},{0.f,-1.f}};
    #pragma unroll
    for (int j = 0; j < 8; ++j) {
        float2 a = v[j], b = v[j + 8];
        v[j] = cadd(a, b);
        v[j + 8] = cmul(csub(a, b), C16[j]);
    }
    #pragma unroll
    for (int h = 0; h < 2; ++h)
        #pragma unroll
        for (int j = 0; j < 4; ++j) {
            int i0 = h * 8 + j;
            float2 a = v[i0], b = v[i0 + 4];
            v[i0] = cadd(a, b);
            v[i0 + 4] = cmul(csub(a, b), C8[j]);
        }
    #pragma unroll
    for (int h = 0; h < 4; ++h)
        #pragma unroll
        for (int j = 0; j < 2; ++j) {
            int i0 = h * 4 + j;
            float2 a = v[i0], b = v[i0 + 2];
            v[i0] = cadd(a, b);
            v[i0 + 2] = cmul(csub(a, b), W4[j]);
        }
    #pragma unroll
    for (int q = 0; q < 8; ++q) {
        float2 a = v[2 * q], b = v[2 * q + 1];
        v[2 * q] = cadd(a, b);
        v[2 * q + 1] = csub(a, b);
    }
}

__device__ __forceinline__ void fft16_inv(float2* v) {
    DECL_C16; DECL_C8;
    const float2 W4[2]  = {{1.f,0.f},{0.f,-1.f}};
    #pragma unroll
    for (int q = 0; q < 8; ++q) {
        float2 a = v[2 * q], b = v[2 * q + 1];
        v[2 * q] = cadd(a, b);
        v[2 * q + 1] = csub(a, b);
    }
    #pragma unroll
    for (int h = 0; h < 4; ++h)
        #pragma unroll
        for (int j = 0; j < 2; ++j) {
            int i0 = h * 4 + j;
            float2 a = v[i0];
            float2 b = cmulc(v[i0 + 2], W4[j]);
            v[i0] = cadd(a, b);
            v[i0 + 2] = csub(a, b);
        }
    #pragma unroll
    for (int h = 0; h < 2; ++h)
        #pragma unroll
        for (int j = 0; j < 4; ++j) {
            int i0 = h * 8 + j;
            float2 a = v[i0];
            float2 b = cmulc(v[i0 + 4], C8[j]);
            v[i0] = cadd(a, b);
            v[i0 + 4] = csub(a, b);
        }
    #pragma unroll
    for (int j = 0; j < 8; ++j) {
        float2 a = v[j];
        float2 b = cmulc(v[j + 8], C16[j]);
        v[j] = cadd(a, b);
        v[j + 8] = csub(a, b);
    }
}

// ---------------------------------------------------------------------------
// Multiscale kernel construction
// ---------------------------------------------------------------------------
__device__ __forceinline__ float build_k(const float* const* kp, int c, int l) {
    int seg, j, s;
    if (l < 64)       { seg = 0; j = l;      s = 1; }
    else if (l < 128) { seg = 1; j = l - 64; s = 1; }
    else {
        int hb = 31 - __clz(l);
        seg = hb - 5;
        j   = l - (1 << hb);
        s   = 1 << (seg - 1);
    }
    const float* kk = kp[seg] + c * KD;
    if (s == 1) return kk[j];
    float coord = ((float)j + 0.5f) / (float)s - 0.5f;
    coord = fminf(fmaxf(coord, 0.0f), 63.0f);
    int lo = (int)floorf(coord);
    int hi = min(lo + 1, 63);
    float w = coord - (float)lo;
    return kk[lo] * (1.0f - w) + kk[hi] * w;
}

__device__ __forceinline__ int brev13(int x) { return (int)(__brev((unsigned)x) >> 19); }

#define BKF_THR 512
__global__ __launch_bounds__(BKF_THR) void build_kf_kernel(
    const float* __restrict__ k0, const float* __restrict__ k1,
    const float* __restrict__ k2, const float* __restrict__ k3,
    const float* __restrict__ k4, const float* __restrict__ k5,
    const float* __restrict__ k6)
{
    extern __shared__ float2 z[];
    __shared__ float red0[BKF_THR], red1[BKF_THR];
    int tid = threadIdx.x;
    int c0 = blockIdx.x * 2, c1 = c0 + 1;
    const float* kp[7] = {k0, k1, k2, k3, k4, k5, k6};

    float s0 = 0.f, s1 = 0.f;
    for (int l = tid; l < N_FFT; l += BKF_THR) {
        if (l < L_SEQ) {
            float v0 = build_k(kp, c0, l);
            float v1 = build_k(kp, c1, l);
            z[PIDX(l)] = make_float2(v0, v1);
            s0 += v0 * v0; s1 += v1 * v1;
        } else {
            z[PIDX(l)] = make_float2(0.f, 0.f);
        }
    }
    red0[tid] = s0; red1[tid] = s1;
    __syncthreads();
    for (int o = BKF_THR / 2; o > 0; o >>= 1) {
        if (tid < o) { red0[tid] += red0[tid + o]; red1[tid] += red1[tid + o]; }
        __syncthreads();
    }
    float inv0 = 1.0f / sqrtf(red0[0]);
    float inv1 = 1.0f / sqrtf(red1[0]);
    for (int l = tid; l < L_SEQ; l += BKF_THR) {
        float2 v = z[PIDX(l)];
        z[PIDX(l)] = make_float2(v.x * inv0, v.y * inv1);
    }

    pass8_fwd<BKF_THR>(z, tid, 12);
    pass8_fwd<BKF_THR>(z, tid, 9);
    pass8_fwd<BKF_THR>(z, tid, 6);
    __syncthreads();
    {
        float2 v[16];
        #pragma unroll
        for (int j = 0; j < 16; ++j) v[j] = z[PIDX(16 * tid + j)];
        fft16_fwd(v);
        #pragma unroll
        for (int j = 0; j < 16; ++j) z[PIDX(16 * tid + j)] = v[j];
    }
    __syncthreads();

    const float hs = 0.5f / (float)N_FFT;
    float2* Kf0 = d_Kf + (size_t)c0 * N_FFT;
    float2* Kf1 = d_Kf + (size_t)c1 * N_FFT;
    for (int j = tid; j < N_FFT; j += BKF_THR) {
        int m  = brev13(j);
        int pm = (N_FFT - m) & (N_FFT - 1);
        int p  = brev13(pm);
        float2 zj = z[PIDX(j)], zp = z[PIDX(p)];
        Kf0[j] = make_float2(hs * (zj.x + zp.x),  hs * (zj.y - zp.y));
        Kf1[j] = make_float2(hs * (zj.y + zp.y), -hs * (zj.x - zp.x));
    }
}

// ---------------------------------------------------------------------------
// W split (fp32 -> fp16 hi + lo)
// ---------------------------------------------------------------------------
__global__ void wsplit_kernel(const float* __restrict__ W) {
    int i = blockIdx.x * blockDim.x + threadIdx.x;
    if (i < DM * DM) {
        float w = W[i];
        __half hi = __float2half(w);
        d_Whf[i] = hi;
        d_Wlf[i] = __float2half(w - __half2float(hi));
    }
}

// ---------------------------------------------------------------------------
// Conv: one block per (channel d, batch-pair). 5 smem sweeps:
//   pass16_fwd(12), pass16_fwd(8),
//   merged middle [shfl stage-4 + fft16 + pointwise + ifft16 + shfl stage-4],
//   pass16_inv(8), pass16_inv(12).
// Vectorized global I/O (LDG.128 for u, STG.128 of 8 packed halves for G).
// ---------------------------------------------------------------------------
#define CONV_THR 512
__global__ __launch_bounds__(CONV_THR, 2) void conv_kernel(
    const float* __restrict__ u, const float* __restrict__ Dp)
{
    extern __shared__ float2 z[];
    int tid = threadIdx.x;
    int d  = blockIdx.y;
    int bp = blockIdx.x;
    int b0 = bp * 2, b1 = b0 + 1;

    const float* u0 = u + ((size_t)b0 * DM + d) * L_SEQ;
    const float* u1 = u + ((size_t)b1 * DM + d) * L_SEQ;

    {   // prologue: 8 contiguous elements per thread, vectorized u loads
        int l0 = 8 * tid;
        float4 a0 = *(const float4*)(u0 + l0);
        float4 a1 = *(const float4*)(u0 + l0 + 4);
        float4 c0 = *(const float4*)(u1 + l0);
        float4 c1 = *(const float4*)(u1 + l0 + 4);
        z[PIDX(l0 + 0)] = make_float2(a0.x, c0.x);
        z[PIDX(l0 + 1)] = make_float2(a0.y, c0.y);
        z[PIDX(l0 + 2)] = make_float2(a0.z, c0.z);
        z[PIDX(l0 + 3)] = make_float2(a0.w, c0.w);
        z[PIDX(l0 + 4)] = make_float2(a1.x, c1.x);
        z[PIDX(l0 + 5)] = make_float2(a1.y, c1.y);
        z[PIDX(l0 + 6)] = make_float2(a1.z, c1.z);
        z[PIDX(l0 + 7)] = make_float2(a1.w, c1.w);
        #pragma unroll
        for (int j = 0; j < 8; ++j)
            z[PIDX(L_SEQ + l0 + j)] = make_float2(0.f, 0.f);
    }

    pass16_fwd(z, tid, 12);
    pass16_fwd(z, tid, 8);
    __syncthreads();

    {   // middle: stage 4 via shfl, stages 3..0 + pointwise + inverse in regs
        DECL_C32;
        int h = tid & 1;
        int base = 16 * tid;
        float2 v[16];
        #pragma unroll
        for (int j = 0; j < 16; ++j) v[j] = z[PIDX(base + j)];
        #pragma unroll
        for (int j = 0; j < 16; ++j) {   // fwd stage 4 (pair tid^1)
            float2 r;
            r.x = __shfl_xor_sync(0xFFFFFFFFu, v[j].x, 1);
            r.y = __shfl_xor_sync(0xFFFFFFFFu, v[j].y, 1);
            float2 s0 = cadd(v[j], r);                    // h=0: a + b
            float2 s1 = cmul(csub(r, v[j]), C32[j]);      // h=1: (a - b) * w
            v[j] = h ? s1 : s0;
        }
        fft16_fwd(v);
        const float4* kf4 = (const float4*)(d_Kf + (size_t)d * N_FFT + base);
        #pragma unroll
        for (int j = 0; j < 8; ++j) {
            float4 kk = kf4[j];
            v[2 * j]     = cmul(v[2 * j],     make_float2(kk.x, kk.y));
            v[2 * j + 1] = cmul(v[2 * j + 1], make_float2(kk.z, kk.w));
        }
        fft16_inv(v);
        #pragma unroll
        for (int j = 0; j < 16; ++j) {   // inv stage 4
            float2 snd = h ? cmulc(v[j], C32[j]) : v[j];
            float2 r;
            r.x = __shfl_xor_sync(0xFFFFFFFFu, snd.x, 1);
            r.y = __shfl_xor_sync(0xFFFFFFFFu, snd.y, 1);
            v[j] = h ? csub(r, snd) : cadd(snd, r);
        }
        #pragma unroll
        for (int j = 0; j < 16; ++j) z[PIDX(base + j)] = v[j];
    }

    pass16_inv(z, tid, 8);
    pass16_inv(z, tid, 12);
    __syncthreads();

    {   // epilogue: +u*D, exact GELU, pack 8 halves -> one STG.128 per row
        float dd = Dp[d];
        int l0 = 8 * tid;
        float4 a0 = *(const float4*)(u0 + l0);
        float4 a1 = *(const float4*)(u0 + l0 + 4);
        float4 c0 = *(const float4*)(u1 + l0);
        float4 c1 = *(const float4*)(u1 + l0 + 4);
        float ua[8] = {a0.x, a0.y, a0.z, a0.w, a1.x, a1.y, a1.z, a1.w};
        float ub[8] = {c0.x, c0.y, c0.z, c0.w, c1.x, c1.y, c1.z, c1.w};
        __half h0[8], h1[8];
        #pragma unroll
        for (int j = 0; j < 8; ++j) {
            float2 v = z[PIDX(l0 + j)];
            h0[j] = __float2half(gelu_exact(v.x + ua[j] * dd));
            h1[j] = __float2half(gelu_exact(v.y + ub[j] * dd));
        }
        *(uint4*)(d_Gf + ((size_t)b0 * DM + d) * L_SEQ + l0) = *(uint4*)h0;
        *(uint4*)(d_Gf + ((size_t)b1 * DM + d) * L_SEQ + l0) = *(uint4*)h1;
    }
}

// ---------------------------------------------------------------------------
// fp16 tensor-core GEMM, 2 passes: out = (Whf + Wlf) * Gf + bias.
// Block tile 128x256x32; 8 warps (2x4), warp tile 64x64; 3-stage cp.async.
// (unchanged from R14)
// ---------------------------------------------------------------------------
#define AP 40
#define BPCH 264
#define A_BYTES (128 * AP * 2)
#define B_BYTES (32 * BPCH * 2)
#define STG_B (2 * A_BYTES + B_BYTES)
#define NSTAGE 3
#define GEMM_SMEM (NSTAGE * STG_B)

__device__ __forceinline__ void cp16(uint32_t dst, const void* src) {
    asm volatile("cp.async.cg.shared.global [%0], [%1], 16;"
                 :: "r"(dst), "l"(src) : "memory");
}
#define CP_COMMIT() asm volatile("cp.async.commit_group;" ::: "memory")
#define CP_WAIT(n)  asm volatile("cp.async.wait_group %0;" :: "n"(n) : "memory")

__device__ __forceinline__ void ldm_x4(uint32_t* r, uint32_t addr) {
    asm volatile("ldmatrix.sync.aligned.m8n8.x4.shared.b16 {%0,%1,%2,%3}, [%4];"
                 : "=r"(r[0]), "=r"(r[1]), "=r"(r[2]), "=r"(r[3]) : "r"(addr));
}
__device__ __forceinline__ void ldm_x4_t(uint32_t* r, uint32_t addr) {
    asm volatile("ldmatrix.sync.aligned.m8n8.x4.trans.shared.b16 {%0,%1,%2,%3}, [%4];"
                 : "=r"(r[0]), "=r"(r[1]), "=r"(r[2]), "=r"(r[3]) : "r"(addr));
}
__device__ __forceinline__ void mma16816h(float* d, const uint32_t* a, const uint32_t* b) {
    asm volatile(
        "mma.sync.aligned.m16n8k16.row.col.f32.f16.f16.f32 "
        "{%0,%1,%2,%3}, {%4,%5,%6,%7}, {%8,%9}, {%0,%1,%2,%3};"
        : "+f"(d[0]), "+f"(d[1]), "+f"(d[2]), "+f"(d[3])
        : "r"(a[0]), "r"(a[1]), "r"(a[2]), "r"(a[3]), "r"(b[0]), "r"(b[1]));
}

__global__ __launch_bounds__(256, 1) void gemm_mma_kernel(
    const float* __restrict__ bias, float* __restrict__ out)
{
    extern __shared__ __align__(16) char sm[];
    int tid = threadIdx.x;
    int wid = tid >> 5, lane = tid & 31;
    int v0 = blockIdx.x * 128;
    int bb = blockIdx.y >> 4;
    int l0 = (blockIdx.y & 15) * 256;

    uint32_t sbase = smem_u32(sm);
    const __half* Wsrc[2] = { d_Whf, d_Wlf };

    float acc[4][8][4];
    #pragma unroll
    for (int i = 0; i < 4; ++i)
        #pragma unroll
        for (int j = 0; j < 8; ++j)
            #pragma unroll
            for (int q = 0; q < 4; ++q) acc[i][j][q] = 0.f;

    auto load_tile = [&](int c, int s) {
        if (c < 32) {
            int k0 = c * 32;
            uint32_t stg = sbase + s * STG_B;
            #pragma unroll
            for (int it = 0; it < 4; ++it) {
                int idx = tid + it * 256;
                int m = idx >> 9, r = (idx >> 2) & 127, c4 = idx & 3;
                const __half* src = Wsrc[m] + (size_t)(v0 + r) * DM + k0 + c4 * 8;
                cp16(stg + m * A_BYTES + r * (AP * 2) + c4 * 16, src);
            }
            #pragma unroll
            for (int it = 0; it < 4; ++it) {
                int idx = tid + it * 256;
                int r = idx >> 5, c4 = idx & 31;
                const __half* src =
                    d_Gf + ((size_t)(bb * DM + k0 + r)) * L_SEQ + l0 + c4 * 8;
                cp16(stg + 2 * A_BYTES + r * (BPCH * 2) + c4 * 16, src);
            }
        }
        CP_COMMIT();
    };

    int wm = (wid >> 2) * 64;
    int wn = (wid & 3) * 64;
    int lr = lane & 15, lc = lane >> 4;

    load_tile(0, 0);
    load_tile(1, 1);
    load_tile(2, 2);

    #pragma unroll 1
    for (int c = 0; c < 32; ++c) {
        int s = c % NSTAGE;
        CP_WAIT(2);
        __syncthreads();

        uint32_t stg = sbase + s * STG_B;
        #pragma unroll
        for (int kk = 0; kk < 2; ++kk) {
            uint32_t aH[4][4], aL[4][4], bF[8][2];
            #pragma unroll
            for (int mi = 0; mi < 4; ++mi) {
                uint32_t off = (uint32_t)((wm + mi * 16 + lr) * (AP * 2) +
                                          (kk * 16 + lc * 8) * 2);
                ldm_x4(aH[mi], stg + off);
                ldm_x4(aL[mi], stg + A_BYTES + off);
            }
            #pragma unroll
            for (int n4 = 0; n4 < 4; ++n4) {
                uint32_t off = (uint32_t)((kk * 16 + lr) * (BPCH * 2) +
                                          (wn + n4 * 16 + lc * 8) * 2);
                uint32_t t4[4];
                ldm_x4_t(t4, stg + 2 * A_BYTES + off);
                bF[n4 * 2][0] = t4[0]; bF[n4 * 2][1] = t4[1];
                bF[n4 * 2 + 1][0] = t4[2]; bF[n4 * 2 + 1][1] = t4[3];
            }
            #pragma unroll
            for (int mi = 0; mi < 4; ++mi)
                #pragma unroll
                for (int nj = 0; nj < 8; ++nj) {
                    mma16816h(acc[mi][nj], aH[mi], bF[nj]);
                    mma16816h(acc[mi][nj], aL[mi], bF[nj]);
                }
        }
        __syncthreads();
        load_tile(c + NSTAGE, s);
    }
    CP_WAIT(0);

    int g = lane >> 2, tg = lane & 3;
    #pragma unroll
    for (int mi = 0; mi < 4; ++mi) {
        int v = v0 + wm + mi * 16 + g;
        float bv0 = bias[v], bv1 = bias[v + 8];
        #pragma unroll
        for (int nj = 0; nj < 8; ++nj) {
            float* op = out + ((size_t)bb * DM + v) * L_SEQ + l0 + wn + nj * 8 + tg * 2;
            float2 o0 = make_float2(acc[mi][nj][0] + bv0, acc[mi][nj][1] + bv0);
            float2 o1 = make_float2(acc[mi][nj][2] + bv1, acc[mi][nj][3] + bv1);
            *(float2*)op = o0;
            *(float2*)(op + 8 * L_SEQ) = o1;
        }
    }
}

// ---------------------------------------------------------------------------
// Launch
// ---------------------------------------------------------------------------
extern "C" void kernel_launch(void* const* d_in, const int* in_sizes, int n_in,
                              void* d_out, int out_size)
{
    const float* u  = (const float*)d_in[0];
    const float* k0 = (const float*)d_in[1];
    const float* k1 = (const float*)d_in[2];
    const float* k2 = (const float*)d_in[3];
    const float* k3 = (const float*)d_in[4];
    const float* k4 = (const float*)d_in[5];
    const float* k5 = (const float*)d_in[6];
    const float* k6 = (const float*)d_in[7];
    const float* Dv = (const float*)d_in[8];
    const float* Wv = (const float*)d_in[9];
    const float* bv = (const float*)d_in[10];
    float* out = (float*)d_out;

    cudaFuncSetAttribute(build_kf_kernel,
                         cudaFuncAttributeMaxDynamicSharedMemorySize, Z_SMEM_BYTES);
    cudaFuncSetAttribute(conv_kernel,
                         cudaFuncAttributeMaxDynamicSharedMemorySize, Z_SMEM_BYTES);
    cudaFuncSetAttribute(gemm_mma_kernel,
                         cudaFuncAttributeMaxDynamicSharedMemorySize, GEMM_SMEM);

    twid_kernel<<<(N_FFT / 2 + 255) / 256, 256>>>();
    wsplit_kernel<<<(DM * DM) / 256, 256>>>(Wv);
    build_kf_kernel<<<DM / 2, BKF_THR, Z_SMEM_BYTES>>>(k0, k1, k2, k3, k4, k5, k6);
    conv_kernel<<<dim3(BATCH / 2, DM), CONV_THR, Z_SMEM_BYTES>>>(u, Dv);
    gemm_mma_kernel<<<dim3(8, 128), 256, GEMM_SMEM>>>(bv, out);
}

// round 17
// speedup vs baseline: 5.2197x; 1.2829x over previous
#include <cuda_runtime.h>
#include <cuda_fp16.h>
#include <math.h>
#include <stdint.h>

// Problem constants
#define L_SEQ   4096
#define N_FFT   8192
#define DM      1024
#define BATCH   8
#define KD      64

// Padded smem indexing: +1 float2 per 16 elements.
#define PIDX(i) ((i) + ((i) >> 4))
#define Z_SMEM_BYTES ((N_FFT + N_FFT / 16) * 8)   // 69632 B

// ---------------------------------------------------------------------------
// Device scratch
// ---------------------------------------------------------------------------
__device__ float2 d_twid[N_FFT / 2];                 // 32 KB
__device__ float2 d_Kf[(size_t)DM * N_FFT];          // spectra (pre-scaled), DIF order
__device__ __half d_Gf[(size_t)BATCH * DM * L_SEQ];  // gelu output, fp16, 64 MB
__device__ __half d_Whf[DM * DM];

__device__ __forceinline__ float2 cmul(float2 a, float2 b) {
    return make_float2(a.x * b.x - a.y * b.y, a.x * b.y + a.y * b.x);
}
__device__ __forceinline__ float2 cmulc(float2 a, float2 w) {  // a * conj(w)
    return make_float2(a.x * w.x + a.y * w.y, a.y * w.x - a.x * w.y);
}
__device__ __forceinline__ float2 cadd(float2 a, float2 b) {
    return make_float2(a.x + b.x, a.y + b.y);
}
__device__ __forceinline__ float2 csub(float2 a, float2 b) {
    return make_float2(a.x - b.x, a.y - b.y);
}
__device__ __forceinline__ float gelu_exact(float x) {
    return 0.5f * x * (1.0f + erff(x * 0.70710678118654752440f));
}
__device__ __forceinline__ uint32_t smem_u32(const void* p) {
    uint32_t a;
    asm("{ .reg .u64 t; cvta.to.shared.u64 t, %1; cvt.u32.u64 %0, t; }"
        : "=r"(a) : "l"(p));
    return a;
}

// Root-of-unity constant tables (forward direction, e^{-i*theta})
#define FC1 0.92387953251128675613f
#define FS1 0.38268343236508977173f
#define FC2 0.70710678118654752440f
#define GC1 0.98078528040323044913f   // cos(pi/16)
#define GS1 0.19509032201612826785f   // sin(pi/16)
#define GC3 0.83146961230254523708f   // cos(3pi/16)
#define GS3 0.55557023301960222474f   // sin(3pi/16)

#define DECL_C16 const float2 C16[8] = {{1.f,0.f},{FC1,-FS1},{FC2,-FC2},{FS1,-FC1}, \
                                        {0.f,-1.f},{-FS1,-FC1},{-FC2,-FC2},{-FC1,-FS1}}
#define DECL_C8  const float2 C8[4]  = {{1.f,0.f},{FC2,-FC2},{0.f,-1.f},{-FC2,-FC2}}
#define DECL_C32 const float2 C32[16] = { \
    {1.f,0.f},{GC1,-GS1},{FC1,-FS1},{GC3,-GS3},{FC2,-FC2},{GS3,-GC3},{FS1,-FC1},{GS1,-GC1}, \
    {0.f,-1.f},{-GS1,-GC1},{-FS1,-FC1},{-GS3,-GC3},{-FC2,-FC2},{-GC3,-GS3},{-FC1,-FS1},{-GC1,-GS1}}

// ---------------------------------------------------------------------------
// Twiddles
// ---------------------------------------------------------------------------
__global__ void twid_kernel() {
    int k = blockIdx.x * blockDim.x + threadIdx.x;
    if (k < N_FFT / 2) {
        double ang = -2.0 * 3.14159265358979323846 * (double)k / (double)N_FFT;
        d_twid[k] = make_float2((float)cos(ang), (float)sin(ang));
    }
}

// ---------------------------------------------------------------------------
// Radix-16 pass: 4 radix-2 DIF stages (lt..lt-3) per smem round trip.
// One twiddle table load per group; all other twiddles derived.
// Requires blockDim == 512 (= N_FFT/16): exactly one group per thread.
// ---------------------------------------------------------------------------
__device__ __forceinline__ void pass16_fwd(float2* __restrict__ z, int tid, int lt) {
    DECL_C16; DECL_C8;
    int s8 = 1 << (lt - 3);
    __syncthreads();
    int o = tid & (s8 - 1);
    int p = ((tid >> (lt - 3)) << (lt + 1)) + o;
    float2 v[16];
    #pragma unroll
    for (int k = 0; k < 16; ++k) v[k] = z[PIDX(p + k * s8)];
    float2 w1 = d_twid[o << (12 - lt)];
    float2 w2 = cmul(w1, w1);
    float2 w4 = cmul(w2, w2);
    float2 w8 = cmul(w4, w4);
    #pragma unroll
    for (int k = 0; k < 8; ++k) {                       // stage lt
        float2 a = v[k], b = v[k + 8];
        v[k] = cadd(a, b);
        v[k + 8] = cmul(csub(a, b), cmul(w1, C16[k]));
    }
    #pragma unroll
    for (int h = 0; h < 2; ++h)                         // stage lt-1
        #pragma unroll
        for (int k = 0; k < 4; ++k) {
            int i0 = h * 8 + k;
            float2 a = v[i0], b = v[i0 + 4];
            v[i0] = cadd(a, b);
            v[i0 + 4] = cmul(csub(a, b), cmul(w2, C8[k]));
        }
    #pragma unroll
    for (int q = 0; q < 4; ++q)                         // stage lt-2
        #pragma unroll
        for (int k = 0; k < 2; ++k) {
            int i0 = q * 4 + k;
            float2 a = v[i0], b = v[i0 + 2];
            v[i0] = cadd(a, b);
            float2 tw = k ? make_float2(w4.y, -w4.x) : w4;   // w4 * (-i)
            v[i0 + 2] = cmul(csub(a, b), tw);
        }
    #pragma unroll
    for (int r = 0; r < 8; ++r) {                       // stage lt-3
        float2 a = v[2 * r], b = v[2 * r + 1];
        v[2 * r] = cadd(a, b);
        v[2 * r + 1] = cmul(csub(a, b), w8);
    }
    #pragma unroll
    for (int k = 0; k < 16; ++k) z[PIDX(p + k * s8)] = v[k];
}

__device__ __forceinline__ void pass16_inv(float2* __restrict__ z, int tid, int lt) {
    DECL_C16; DECL_C8;
    int s8 = 1 << (lt - 3);
    __syncthreads();
    int o = tid & (s8 - 1);
    int p = ((tid >> (lt - 3)) << (lt + 1)) + o;
    float2 v[16];
    #pragma unroll
    for (int k = 0; k < 16; ++k) v[k] = z[PIDX(p + k * s8)];
    float2 w1 = d_twid[o << (12 - lt)];
    float2 w2 = cmul(w1, w1);
    float2 w4 = cmul(w2, w2);
    float2 w8 = cmul(w4, w4);
    #pragma unroll
    for (int r = 0; r < 8; ++r) {                       // stage lt-3
        float2 a = v[2 * r];
        float2 b = cmulc(v[2 * r + 1], w8);
        v[2 * r] = cadd(a, b);
        v[2 * r + 1] = csub(a, b);
    }
    #pragma unroll
    for (int q = 0; q < 4; ++q)                         // stage lt-2
        #pragma unroll
        for (int k = 0; k < 2; ++k) {
            int i0 = q * 4 + k;
            float2 tw = k ? make_float2(w4.y, -w4.x) : w4;
            float2 a = v[i0];
            float2 b = cmulc(v[i0 + 2], tw);
            v[i0] = cadd(a, b);
            v[i0 + 2] = csub(a, b);
        }
    #pragma unroll
    for (int h = 0; h < 2; ++h)                         // stage lt-1
        #pragma unroll
        for (int k = 0; k < 4; ++k) {
            int i0 = h * 8 + k;
            float2 a = v[i0];
            float2 b = cmulc(v[i0 + 4], cmul(w2, C8[k]));
            v[i0] = cadd(a, b);
            v[i0 + 4] = csub(a, b);
        }
    #pragma unroll
    for (int k = 0; k < 8; ++k) {                       // stage lt
        float2 a = v[k];
        float2 b = cmulc(v[k + 8], cmul(w1, C16[k]));
        v[k] = cadd(a, b);
        v[k + 8] = csub(a, b);
    }
    #pragma unroll
    for (int k = 0; k < 16; ++k) z[PIDX(p + k * s8)] = v[k];
}

// ---------------------------------------------------------------------------
// Register-resident 16-point FFT (DIF stages 3..0 / DIT stages 0..3).
// ---------------------------------------------------------------------------
__device__ __forceinline__ void fft16_fwd(float2* v) {
    DECL_C16; DECL_C8;
    const float2 W4[2]  = {{1.f,0.f},{0.f,-1.f}};
    #pragma unroll
    for (int j = 0; j < 8; ++j) {
        float2 a = v[j], b = v[j + 8];
        v[j] = cadd(a, b);
        v[j + 8] = cmul(csub(a, b), C16[j]);
    }
    #pragma unroll
    for (int h = 0; h < 2; ++h)
        #pragma unroll
        for (int j = 0; j < 4; ++j) {
            int i0 = h * 8 + j;
            float2 a = v[i0], b = v[i0 + 4];
            v[i0] = cadd(a, b);
            v[i0 + 4] = cmul(csub(a, b), C8[j]);
        }
    #pragma unroll
    for (int h = 0; h < 4; ++h)
        #pragma unroll
        for (int j = 0; j < 2; ++j) {
            int i0 = h * 4 + j;
            float2 a = v[i0], b = v[i0 + 2];
            v[i0] = cadd(a, b);
            v[i0 + 2] = cmul(csub(a, b), W4[j]);
        }
    #pragma unroll
    for (int q = 0; q < 8; ++q) {
        float2 a = v[2 * q], b = v[2 * q + 1];
        v[2 * q] = cadd(a, b);
        v[2 * q + 1] = csub(a, b);
    }
}

__device__ __forceinline__ void fft16_inv(float2* v) {
    DECL_C16; DECL_C8;
    const float2 W4[2]  = {{1.f,0.f},{0.f,-1.f}};
    #pragma unroll
    for (int q = 0; q < 8; ++q) {
        float2 a = v[2 * q], b = v[2 * q + 1];
        v[2 * q] = cadd(a, b);
        v[2 * q + 1] = csub(a, b);
    }
    #pragma unroll
    for (int h = 0; h < 4; ++h)
        #pragma unroll
        for (int j = 0; j < 2; ++j) {
            int i0 = h * 4 + j;
            float2 a = v[i0];
            float2 b = cmulc(v[i0 + 2], W4[j]);
            v[i0] = cadd(a, b);
            v[i0 + 2] = csub(a, b);
        }
    #pragma unroll
    for (int h = 0; h < 2; ++h)
        #pragma unroll
        for (int j = 0; j < 4; ++j) {
            int i0 = h * 8 + j;
            float2 a = v[i0];
            float2 b = cmulc(v[i0 + 4], C8[j]);
            v[i0] = cadd(a, b);
            v[i0 + 4] = csub(a, b);
        }
    #pragma unroll
    for (int j = 0; j < 8; ++j) {
        float2 a = v[j];
        float2 b = cmulc(v[j + 8], C16[j]);
        v[j] = cadd(a, b);
        v[j + 8] = csub(a, b);
    }
}

// ---------------------------------------------------------------------------
// Multiscale kernel construction
// ---------------------------------------------------------------------------
__device__ __forceinline__ float build_k(const float* const* kp, int c, int l) {
    int seg, j, s;
    if (l < 64)       { seg = 0; j = l;      s = 1; }
    else if (l < 128) { seg = 1; j = l - 64; s = 1; }
    else {
        int hb = 31 - __clz(l);
        seg = hb - 5;
        j   = l - (1 << hb);
        s   = 1 << (seg - 1);
    }
    const float* kk = kp[seg] + c * KD;
    if (s == 1) return kk[j];
    float coord = ((float)j + 0.5f) / (float)s - 0.5f;
    coord = fminf(fmaxf(coord, 0.0f), 63.0f);
    int lo = (int)floorf(coord);
    int hi = min(lo + 1, 63);
    float w = coord - (float)lo;
    return kk[lo] * (1.0f - w) + kk[hi] * w;
}

__device__ __forceinline__ int brev13(int x) { return (int)(__brev((unsigned)x) >> 19); }

#define BKF_THR 512
__global__ __launch_bounds__(BKF_THR) void build_kf_kernel(
    const float* __restrict__ k0, const float* __restrict__ k1,
    const float* __restrict__ k2, const float* __restrict__ k3,
    const float* __restrict__ k4, const float* __restrict__ k5,
    const float* __restrict__ k6)
{
    extern __shared__ float2 z[];
    __shared__ float red0[BKF_THR], red1[BKF_THR];
    int tid = threadIdx.x;
    int c0 = blockIdx.x * 2, c1 = c0 + 1;
    const float* kp[7] = {k0, k1, k2, k3, k4, k5, k6};

    float s0 = 0.f, s1 = 0.f;
    for (int l = tid; l < N_FFT; l += BKF_THR) {
        if (l < L_SEQ) {
            float v0 = build_k(kp, c0, l);
            float v1 = build_k(kp, c1, l);
            z[PIDX(l)] = make_float2(v0, v1);
            s0 += v0 * v0; s1 += v1 * v1;
        } else {
            z[PIDX(l)] = make_float2(0.f, 0.f);
        }
    }
    red0[tid] = s0; red1[tid] = s1;
    __syncthreads();
    for (int o = BKF_THR / 2; o > 0; o >>= 1) {
        if (tid < o) { red0[tid] += red0[tid + o]; red1[tid] += red1[tid + o]; }
        __syncthreads();
    }
    float inv0 = 1.0f / sqrtf(red0[0]);
    float inv1 = 1.0f / sqrtf(red1[0]);
    for (int l = tid; l < L_SEQ; l += BKF_THR) {
        float2 v = z[PIDX(l)];
        z[PIDX(l)] = make_float2(v.x * inv0, v.y * inv1);
    }

    pass16_fwd(z, tid, 12);
    pass16_fwd(z, tid, 8);
    __syncthreads();
    {   // stage 4 via shfl (pair tid^1), then stages 3..0 in registers
        DECL_C32;
        int h = tid & 1;
        int base = 16 * tid;
        float2 v[16];
        #pragma unroll
        for (int j = 0; j < 16; ++j) v[j] = z[PIDX(base + j)];
        #pragma unroll
        for (int j = 0; j < 16; ++j) {
            float2 r;
            r.x = __shfl_xor_sync(0xFFFFFFFFu, v[j].x, 1);
            r.y = __shfl_xor_sync(0xFFFFFFFFu, v[j].y, 1);
            float2 t0 = cadd(v[j], r);
            float2 t1 = cmul(csub(r, v[j]), C32[j]);
            v[j] = h ? t1 : t0;
        }
        fft16_fwd(v);
        #pragma unroll
        for (int j = 0; j < 16; ++j) z[PIDX(base + j)] = v[j];
    }
    __syncthreads();

    const float hs = 0.5f / (float)N_FFT;
    float2* Kf0 = d_Kf + (size_t)c0 * N_FFT;
    float2* Kf1 = d_Kf + (size_t)c1 * N_FFT;
    for (int j = tid; j < N_FFT; j += BKF_THR) {
        int m  = brev13(j);
        int pm = (N_FFT - m) & (N_FFT - 1);
        int p  = brev13(pm);
        float2 zj = z[PIDX(j)], zp = z[PIDX(p)];
        Kf0[j] = make_float2(hs * (zj.x + zp.x),  hs * (zj.y - zp.y));
        Kf1[j] = make_float2(hs * (zj.y + zp.y), -hs * (zj.x - zp.x));
    }
}

// ---------------------------------------------------------------------------
// W -> fp16
// ---------------------------------------------------------------------------
__global__ void wsplit_kernel(const float* __restrict__ W) {
    int i = blockIdx.x * blockDim.x + threadIdx.x;
    if (i < DM * DM) d_Whf[i] = __float2half(W[i]);
}

// ---------------------------------------------------------------------------
// Conv: one block per (channel d, batch-pair). 5 smem sweeps (unchanged R15).
// ---------------------------------------------------------------------------
#define CONV_THR 512
__global__ __launch_bounds__(CONV_THR, 2) void conv_kernel(
    const float* __restrict__ u, const float* __restrict__ Dp)
{
    extern __shared__ float2 z[];
    int tid = threadIdx.x;
    int d  = blockIdx.y;
    int bp = blockIdx.x;
    int b0 = bp * 2, b1 = b0 + 1;

    const float* u0 = u + ((size_t)b0 * DM + d) * L_SEQ;
    const float* u1 = u + ((size_t)b1 * DM + d) * L_SEQ;

    {   // prologue
        int l0 = 8 * tid;
        float4 a0 = *(const float4*)(u0 + l0);
        float4 a1 = *(const float4*)(u0 + l0 + 4);
        float4 c0 = *(const float4*)(u1 + l0);
        float4 c1 = *(const float4*)(u1 + l0 + 4);
        z[PIDX(l0 + 0)] = make_float2(a0.x, c0.x);
        z[PIDX(l0 + 1)] = make_float2(a0.y, c0.y);
        z[PIDX(l0 + 2)] = make_float2(a0.z, c0.z);
        z[PIDX(l0 + 3)] = make_float2(a0.w, c0.w);
        z[PIDX(l0 + 4)] = make_float2(a1.x, c1.x);
        z[PIDX(l0 + 5)] = make_float2(a1.y, c1.y);
        z[PIDX(l0 + 6)] = make_float2(a1.z, c1.z);
        z[PIDX(l0 + 7)] = make_float2(a1.w, c1.w);
        #pragma unroll
        for (int j = 0; j < 8; ++j)
            z[PIDX(L_SEQ + l0 + j)] = make_float2(0.f, 0.f);
    }

    pass16_fwd(z, tid, 12);
    pass16_fwd(z, tid, 8);
    __syncthreads();

    {   // middle: stage 4 via shfl, stages 3..0 + pointwise + inverse in regs
        DECL_C32;
        int h = tid & 1;
        int base = 16 * tid;
        float2 v[16];
        #pragma unroll
        for (int j = 0; j < 16; ++j) v[j] = z[PIDX(base + j)];
        #pragma unroll
        for (int j = 0; j < 16; ++j) {
            float2 r;
            r.x = __shfl_xor_sync(0xFFFFFFFFu, v[j].x, 1);
            r.y = __shfl_xor_sync(0xFFFFFFFFu, v[j].y, 1);
            float2 t0 = cadd(v[j], r);
            float2 t1 = cmul(csub(r, v[j]), C32[j]);
            v[j] = h ? t1 : t0;
        }
        fft16_fwd(v);
        const float4* kf4 = (const float4*)(d_Kf + (size_t)d * N_FFT + base);
        #pragma unroll
        for (int j = 0; j < 8; ++j) {
            float4 kk = kf4[j];
            v[2 * j]     = cmul(v[2 * j],     make_float2(kk.x, kk.y));
            v[2 * j + 1] = cmul(v[2 * j + 1], make_float2(kk.z, kk.w));
        }
        fft16_inv(v);
        #pragma unroll
        for (int j = 0; j < 16; ++j) {
            float2 snd = h ? cmulc(v[j], C32[j]) : v[j];
            float2 r;
            r.x = __shfl_xor_sync(0xFFFFFFFFu, snd.x, 1);
            r.y = __shfl_xor_sync(0xFFFFFFFFu, snd.y, 1);
            v[j] = h ? csub(r, snd) : cadd(snd, r);
        }
        #pragma unroll
        for (int j = 0; j < 16; ++j) z[PIDX(base + j)] = v[j];
    }

    pass16_inv(z, tid, 8);
    pass16_inv(z, tid, 12);
    __syncthreads();

    {   // epilogue
        float dd = Dp[d];
        int l0 = 8 * tid;
        float4 a0 = *(const float4*)(u0 + l0);
        float4 a1 = *(const float4*)(u0 + l0 + 4);
        float4 c0 = *(const float4*)(u1 + l0);
        float4 c1 = *(const float4*)(u1 + l0 + 4);
        float ua[8] = {a0.x, a0.y, a0.z, a0.w, a1.x, a1.y, a1.z, a1.w};
        float ub[8] = {c0.x, c0.y, c0.z, c0.w, c1.x, c1.y, c1.z, c1.w};
        __half h0[8], h1[8];
        #pragma unroll
        for (int j = 0; j < 8; ++j) {
            float2 v = z[PIDX(l0 + j)];
            h0[j] = __float2half(gelu_exact(v.x + ua[j] * dd));
            h1[j] = __float2half(gelu_exact(v.y + ub[j] * dd));
        }
        *(uint4*)(d_Gf + ((size_t)b0 * DM + d) * L_SEQ + l0) = *(uint4*)h0;
        *(uint4*)(d_Gf + ((size_t)b1 * DM + d) * L_SEQ + l0) = *(uint4*)h1;
    }
}

// ---------------------------------------------------------------------------
// fp16 tensor-core GEMM, SINGLE pass: out = Whf * Gf + bias.
// Block tile 128x256x32; 8 warps (2x4), warp tile 64x64; 3-stage cp.async.
// ---------------------------------------------------------------------------
#define AP 40
#define BPCH 264
#define A_BYTES (128 * AP * 2)          // 10240
#define B_BYTES (32 * BPCH * 2)         // 16896
#define STG_B (A_BYTES + B_BYTES)       // 27136
#define NSTAGE 3
#define GEMM_SMEM (NSTAGE * STG_B)      // 81408

__device__ __forceinline__ void cp16(uint32_t dst, const void* src) {
    asm volatile("cp.async.cg.shared.global [%0], [%1], 16;"
                 :: "r"(dst), "l"(src) : "memory");
}
#define CP_COMMIT() asm volatile("cp.async.commit_group;" ::: "memory")
#define CP_WAIT(n)  asm volatile("cp.async.wait_group %0;" :: "n"(n) : "memory")

__device__ __forceinline__ void ldm_x4(uint32_t* r, uint32_t addr) {
    asm volatile("ldmatrix.sync.aligned.m8n8.x4.shared.b16 {%0,%1,%2,%3}, [%4];"
                 : "=r"(r[0]), "=r"(r[1]), "=r"(r[2]), "=r"(r[3]) : "r"(addr));
}
__device__ __forceinline__ void ldm_x4_t(uint32_t* r, uint32_t addr) {
    asm volatile("ldmatrix.sync.aligned.m8n8.x4.trans.shared.b16 {%0,%1,%2,%3}, [%4];"
                 : "=r"(r[0]), "=r"(r[1]), "=r"(r[2]), "=r"(r[3]) : "r"(addr));
}
__device__ __forceinline__ void mma16816h(float* d, const uint32_t* a, const uint32_t* b) {
    asm volatile(
        "mma.sync.aligned.m16n8k16.row.col.f32.f16.f16.f32 "
        "{%0,%1,%2,%3}, {%4,%5,%6,%7}, {%8,%9}, {%0,%1,%2,%3};"
        : "+f"(d[0]), "+f"(d[1]), "+f"(d[2]), "+f"(d[3])
        : "r"(a[0]), "r"(a[1]), "r"(a[2]), "r"(a[3]), "r"(b[0]), "r"(b[1]));
}

__global__ __launch_bounds__(256, 1) void gemm_mma_kernel(
    const float* __restrict__ bias, float* __restrict__ out)
{
    extern __shared__ __align__(16) char sm[];
    int tid = threadIdx.x;
    int wid = tid >> 5, lane = tid & 31;
    int v0 = blockIdx.x * 128;
    int bb = blockIdx.y >> 4;
    int l0 = (blockIdx.y & 15) * 256;

    uint32_t sbase = smem_u32(sm);

    float acc[4][8][4];
    #pragma unroll
    for (int i = 0; i < 4; ++i)
        #pragma unroll
        for (int j = 0; j < 8; ++j)
            #pragma unroll
            for (int q = 0; q < 4; ++q) acc[i][j][q] = 0.f;

    auto load_tile = [&](int c, int s) {
        if (c < 32) {
            int k0 = c * 32;
            uint32_t stg = sbase + s * STG_B;
            #pragma unroll
            for (int it = 0; it < 2; ++it) {             // A: Whf 128x32
                int idx = tid + it * 256;
                int r = idx >> 2, c4 = idx & 3;
                const __half* src = d_Whf + (size_t)(v0 + r) * DM + k0 + c4 * 8;
                cp16(stg + r * (AP * 2) + c4 * 16, src);
            }
            #pragma unroll
            for (int it = 0; it < 4; ++it) {             // B: Gf 32x256
                int idx = tid + it * 256;
                int r = idx >> 5, c4 = idx & 31;
                const __half* src =
                    d_Gf + ((size_t)(bb * DM + k0 + r)) * L_SEQ + l0 + c4 * 8;
                cp16(stg + A_BYTES + r * (BPCH * 2) + c4 * 16, src);
            }
        }
        CP_COMMIT();
    };

    int wm = (wid >> 2) * 64;
    int wn = (wid & 3) * 64;
    int lr = lane & 15, lc = lane >> 4;

    load_tile(0, 0);
    load_tile(1, 1);
    load_tile(2, 2);

    #pragma unroll 1
    for (int c = 0; c < 32; ++c) {
        int s = c % NSTAGE;
        CP_WAIT(2);
        __syncthreads();

        uint32_t stg = sbase + s * STG_B;
        #pragma unroll
        for (int kk = 0; kk < 2; ++kk) {
            uint32_t aH[4][4], bF[8][2];
            #pragma unroll
            for (int mi = 0; mi < 4; ++mi) {
                uint32_t off = (uint32_t)((wm + mi * 16 + lr) * (AP * 2) +
                                          (kk * 16 + lc * 8) * 2);
                ldm_x4(aH[mi], stg + off);
            }
            #pragma unroll
            for (int n4 = 0; n4 < 4; ++n4) {
                uint32_t off = (uint32_t)((kk * 16 + lr) * (BPCH * 2) +
                                          (wn + n4 * 16 + lc * 8) * 2);
                uint32_t t4[4];
                ldm_x4_t(t4, stg + A_BYTES + off);
                bF[n4 * 2][0] = t4[0]; bF[n4 * 2][1] = t4[1];
                bF[n4 * 2 + 1][0] = t4[2]; bF[n4 * 2 + 1][1] = t4[3];
            }
            #pragma unroll
            for (int mi = 0; mi < 4; ++mi)
                #pragma unroll
                for (int nj = 0; nj < 8; ++nj)
                    mma16816h(acc[mi][nj], aH[mi], bF[nj]);
        }
        __syncthreads();
        load_tile(c + NSTAGE, s);
    }
    CP_WAIT(0);

    int g = lane >> 2, tg = lane & 3;
    #pragma unroll
    for (int mi = 0; mi < 4; ++mi) {
        int v = v0 + wm + mi * 16 + g;
        float bv0 = bias[v], bv1 = bias[v + 8];
        #pragma unroll
        for (int nj = 0; nj < 8; ++nj) {
            float* op = out + ((size_t)bb * DM + v) * L_SEQ + l0 + wn + nj * 8 + tg * 2;
            float2 o0 = make_float2(acc[mi][nj][0] + bv0, acc[mi][nj][1] + bv0);
            float2 o1 = make_float2(acc[mi][nj][2] + bv1, acc[mi][nj][3] + bv1);
            *(float2*)op = o0;
            *(float2*)(op + 8 * L_SEQ) = o1;
        }
    }
}

// ---------------------------------------------------------------------------
// Launch
// ---------------------------------------------------------------------------
extern "C" void kernel_launch(void* const* d_in, const int* in_sizes, int n_in,
                              void* d_out, int out_size)
{
    const float* u  = (const float*)d_in[0];
    const float* k0 = (const float*)d_in[1];
    const float* k1 = (const float*)d_in[2];
    const float* k2 = (const float*)d_in[3];
    const float* k3 = (const float*)d_in[4];
    const float* k4 = (const float*)d_in[5];
    const float* k5 = (const float*)d_in[6];
    const float* k6 = (const float*)d_in[7];
    const float* Dv = (const float*)d_in[8];
    const float* Wv = (const float*)d_in[9];
    const float* bv = (const float*)d_in[10];
    float* out = (float*)d_out;

    cudaFuncSetAttribute(build_kf_kernel,
                         cudaFuncAttributeMaxDynamicSharedMemorySize, Z_SMEM_BYTES);
    cudaFuncSetAttribute(conv_kernel,
                         cudaFuncAttributeMaxDynamicSharedMemorySize, Z_SMEM_BYTES);
    cudaFuncSetAttribute(gemm_mma_kernel,
                         cudaFuncAttributeMaxDynamicSharedMemorySize, GEMM_SMEM);

    twid_kernel<<<(N_FFT / 2 + 255) / 256, 256>>>();
    wsplit_kernel<<<(DM * DM) / 256, 256>>>(Wv);
    build_kf_kernel<<<DM / 2, BKF_THR, Z_SMEM_BYTES>>>(k0, k1, k2, k3, k4, k5, k6);
    conv_kernel<<<dim3(BATCH / 2, DM), CONV_THR, Z_SMEM_BYTES>>>(u, Dv);
    gemm_mma_kernel<<<dim3(8, 128), 256, GEMM_SMEM>>>(bv, out);
}